// round 5
// baseline (speedup 1.0000x reference)
#include <cuda_runtime.h>
#include <cuda_bf16.h>
#include <math.h>

// ---------------- problem constants ----------------
#define BB   4          // batch
#define TT   4          // temporal
#define HH   56
#define WW_  56
#define CC   256
#define NHD  8
#define HD   32
#define WS_  7
#define SS_  3
#define NTOK 49         // WS*WS
#define HID_ 1024
#define GH   224        // T*H
#define GW   56
#define NWH  32         // GH/WS
#define NWW  8          // GW/WS
#define NW   256        // windows per batch
#define BW   1024       // B*NW
#define MROWS (BW*NTOK)         // 50176
#define LL   (TT*HH*WW_)        // 12544
#define BLC  (BB*LL*CC)         // 12845056

// ---------------- scratch (no cudaMalloc allowed) ----------------
__device__ float g_xw  [MROWS * CC];     // LN1 + shifted windows
__device__ float g_qkv [MROWS * 3*CC];   // qkv
__device__ float g_y   [MROWS * CC];     // attention out (window order)
__device__ float g_x1m [BB*LL*CC];       // x1 + attn (token order)
__device__ float g_xn2 [BB*LL*CC];       // LN2(x1m)
__device__ float g_h   [BB*LL*HID_];     // mlp hidden

// ---------------- LN helpers ----------------
__device__ __forceinline__ void block_ln_stats(float v, float& mean, float& rstd) {
    float s = v, sq = v * v;
    #pragma unroll
    for (int o = 16; o; o >>= 1) {
        s  += __shfl_xor_sync(0xffffffffu, s,  o);
        sq += __shfl_xor_sync(0xffffffffu, sq, o);
    }
    __shared__ float s1[8], s2[8];
    int lane = threadIdx.x & 31, wid = threadIdx.x >> 5;
    if (lane == 0) { s1[wid] = s; s2[wid] = sq; }
    __syncthreads();
    float ts = 0.f, tq = 0.f;
    #pragma unroll
    for (int i = 0; i < 8; i++) { ts += s1[i]; tq += s2[i]; }
    mean = ts * (1.0f / CC);
    float var = tq * (1.0f / CC) - mean * mean;
    rstd = rsqrtf(var + 1e-5f);
}

// LN1 + cyclic shift + window partition.  one block per window-order row.
__global__ __launch_bounds__(256) void k_ln1_shift_win(
    const float* __restrict__ x1, const float* __restrict__ g, const float* __restrict__ b)
{
    int row = blockIdx.x;          // window-order row
    int c = threadIdx.x;
    int bw = row / NTOK, n = row - bw * NTOK;
    int bat = bw >> 8, w = bw & 255;
    int wh = w >> 3, ww = w & 7;
    int hs = wh * WS_ + n / WS_;
    int ws = ww * WS_ + n % WS_;
    int h0 = hs + SS_; if (h0 >= GH) h0 -= GH;
    int w0 = ws + SS_; if (w0 >= GW) w0 -= GW;
    const float* src = x1 + ((size_t)bat * LL + (size_t)h0 * GW + w0) * CC;
    float v = src[c];
    float m, rs; block_ln_stats(v, m, rs);
    g_xw[(size_t)row * CC + c] = (v - m) * rs * g[c] + b[c];
}

// plain LN (token order): g_xn2 = LN2(g_x1m)
__global__ __launch_bounds__(256) void k_ln2(
    const float* __restrict__ g, const float* __restrict__ b)
{
    int row = blockIdx.x;
    int c = threadIdx.x;
    float v = g_x1m[(size_t)row * CC + c];
    float m, rs; block_ln_stats(v, m, rs);
    g_xn2[(size_t)row * CC + c] = (v - m) * rs * g[c] + b[c];
}

// ---------------- tiled NT SGEMM: C[M,N] = A[M,K] @ W[N,K]^T + bias ----------------
// EPI: 0 plain, 1 gelu, 2 residual-add(res)->Cout, 3 proj (window reverse+unshift,
//      write y to out2[optional], Cout = res + val at scattered dst)
#define BM 128
#define BN 128
#define BKK 8

template<int EPI>
__global__ __launch_bounds__(256) void k_gemm_nt(
    const float* __restrict__ A, const float* __restrict__ Wt,
    const float* __restrict__ bias, float* __restrict__ Cout,
    int M, int N, int K,
    const float* __restrict__ res, float* __restrict__ out2)
{
    __shared__ float As[BKK][BM + 4];
    __shared__ float Bs[BKK][BN + 4];
    int t = threadIdx.x;
    int tx = t & 15, ty = t >> 4;
    int m0 = blockIdx.y * BM, n0 = blockIdx.x * BN;

    float acc[8][8];
    #pragma unroll
    for (int i = 0; i < 8; i++)
        #pragma unroll
        for (int j = 0; j < 8; j++) acc[i][j] = 0.f;

    int lrow = t >> 1;            // 0..127
    int lc4  = (t & 1) * 4;       // 0 or 4
    const float* Ag = A  + (size_t)(m0 + lrow) * K + lc4;
    const float* Wg = Wt + (size_t)(n0 + lrow) * K + lc4;

    for (int k0 = 0; k0 < K; k0 += BKK) {
        float4 av = *(const float4*)(Ag + k0);
        float4 bv = *(const float4*)(Wg + k0);
        As[lc4 + 0][lrow] = av.x; As[lc4 + 1][lrow] = av.y;
        As[lc4 + 2][lrow] = av.z; As[lc4 + 3][lrow] = av.w;
        Bs[lc4 + 0][lrow] = bv.x; Bs[lc4 + 1][lrow] = bv.y;
        Bs[lc4 + 2][lrow] = bv.z; Bs[lc4 + 3][lrow] = bv.w;
        __syncthreads();
        #pragma unroll
        for (int kk = 0; kk < BKK; kk++) {
            float a[8], bfr[8];
            #pragma unroll
            for (int i = 0; i < 8; i++) a[i] = As[kk][ty * 8 + i];
            #pragma unroll
            for (int j = 0; j < 8; j++) bfr[j] = Bs[kk][tx * 8 + j];
            #pragma unroll
            for (int i = 0; i < 8; i++)
                #pragma unroll
                for (int j = 0; j < 8; j++)
                    acc[i][j] = fmaf(a[i], bfr[j], acc[i][j]);
        }
        __syncthreads();
    }

    #pragma unroll
    for (int i = 0; i < 8; i++) {
        int r = m0 + ty * 8 + i;
        size_t dstrow = 0;
        if (EPI == 3) {
            int bw = r / NTOK, n = r - bw * NTOK;
            int bat = bw >> 8, w = bw & 255;
            int hs = (w >> 3) * WS_ + n / WS_;
            int ws = (w & 7) * WS_ + n % WS_;
            int h0 = hs + SS_; if (h0 >= GH) h0 -= GH;
            int w0 = ws + SS_; if (w0 >= GW) w0 -= GW;
            dstrow = ((size_t)bat * LL + (size_t)h0 * GW + w0) * CC;
        }
        #pragma unroll
        for (int j = 0; j < 8; j++) {
            int c = n0 + tx * 8 + j;
            float v = acc[i][j] + bias[c];
            if (EPI == 0) {
                Cout[(size_t)r * N + c] = v;
            } else if (EPI == 1) {
                Cout[(size_t)r * N + c] = 0.5f * v * (1.0f + erff(v * 0.70710678118654752f));
            } else if (EPI == 2) {
                size_t o = (size_t)r * N + c;
                Cout[o] = res[o] + v;
            } else { // proj
                if (out2) out2[dstrow + c] = v;
                Cout[dstrow + c] = res[dstrow + c] + v;
            }
        }
    }
}

// ---------------- window attention: one block per (window, head) ----------------
__global__ __launch_bounds__(128) void k_attn(const float* __restrict__ rpb)
{
    int bw = blockIdx.x >> 3;
    int h  = blockIdx.x & 7;
    __shared__ float qs[NTOK][HD + 1];
    __shared__ float ks[NTOK][HD + 1];
    __shared__ float vs[NTOK][HD + 1];
    __shared__ float S [NTOK][NTOK + 3];
    __shared__ float bias_s[169];
    __shared__ int   reg_s[NTOK];
    int t = threadIdx.x;
    const float scale = 0.17677669529663687f; // 32^-0.5

    const float* base = g_qkv + (size_t)bw * NTOK * (3 * CC) + h * HD;
    for (int idx = t; idx < NTOK * HD; idx += 128) {
        int n = idx >> 5, d = idx & 31;
        const float* p = base + (size_t)n * (3 * CC);
        qs[n][d] = p[d] * scale;
        ks[n][d] = p[CC + d];
        vs[n][d] = p[2 * CC + d];
    }
    // FIX: 169 entries, 128 threads -> must loop (was `if (t<169)`, leaving
    // bias_s[128..168] uninitialized)
    for (int idx = t; idx < 169; idx += 128) bias_s[idx] = rpb[idx * NHD + h];
    if (t < NTOK) {
        int w = bw & 255;
        int hs = (w >> 3) * WS_ + t / WS_;
        int ws = (w & 7) * WS_ + t % WS_;
        int rc = hs < (GH - WS_) ? 0 : (hs < (GH - SS_) ? 1 : 2);
        int cc = ws < (GW - WS_) ? 0 : (ws < (GW - SS_) ? 1 : 2);
        reg_s[t] = rc * 3 + cc;
    }
    __syncthreads();

    for (int idx = t; idx < NTOK * NTOK; idx += 128) {
        int i = idx / NTOK, j = idx - i * NTOK;
        float s = 0.f;
        #pragma unroll
        for (int d = 0; d < HD; d++) s = fmaf(qs[i][d], ks[j][d], s);
        int yi = i / 7, xi = i - yi * 7, yj = j / 7, xj = j - yj * 7;
        s += bias_s[(yi - yj + 6) * 13 + (xi - xj + 6)];
        if (reg_s[i] != reg_s[j]) s -= 100.f;
        S[i][j] = s;
    }
    __syncthreads();

    int wid = t >> 5, lane = t & 31;
    for (int i = wid; i < NTOK; i += 4) {
        float v0 = S[i][lane];
        float v1 = (lane < NTOK - 32) ? S[i][lane + 32] : -1e30f;
        float mx = fmaxf(v0, v1);
        #pragma unroll
        for (int o = 16; o; o >>= 1) mx = fmaxf(mx, __shfl_xor_sync(0xffffffffu, mx, o));
        float e0 = __expf(v0 - mx);
        float e1 = (lane < NTOK - 32) ? __expf(v1 - mx) : 0.f;
        float sm = e0 + e1;
        #pragma unroll
        for (int o = 16; o; o >>= 1) sm += __shfl_xor_sync(0xffffffffu, sm, o);
        float inv = 1.f / sm;
        S[i][lane] = e0 * inv;
        if (lane < NTOK - 32) S[i][lane + 32] = e1 * inv;
    }
    __syncthreads();

    float* yout = g_y + (size_t)bw * NTOK * CC + h * HD;
    for (int idx = t; idx < NTOK * HD; idx += 128) {
        int i = idx >> 5, d = idx & 31;
        float s = 0.f;
        #pragma unroll
        for (int j = 0; j < NTOK; j++) s = fmaf(S[i][j], vs[j][d], s);
        yout[(size_t)i * CC + d] = s;
    }
}

// ---------------- launch ----------------
extern "C" void kernel_launch(void* const* d_in, const int* in_sizes, int n_in,
                              void* d_out, int out_size)
{
    const float* x1    = (const float*)d_in[0];
    const float* n1g   = (const float*)d_in[2];
    const float* n1b   = (const float*)d_in[3];
    const float* qkvw  = (const float*)d_in[4];
    const float* qkvb  = (const float*)d_in[5];
    const float* projw = (const float*)d_in[6];
    const float* projb = (const float*)d_in[7];
    const float* rpb   = (const float*)d_in[8];
    const float* n2g   = (const float*)d_in[9];
    const float* n2b   = (const float*)d_in[10];
    const float* fc1w  = (const float*)d_in[11];
    const float* fc1b  = (const float*)d_in[12];
    const float* fc2w  = (const float*)d_in[13];
    const float* fc2b  = (const float*)d_in[14];
    float* out = (float*)d_out;
    float* out2 = (out_size >= 2 * BLC) ? out + BLC : nullptr;

    float *p_xw, *p_qkv, *p_y, *p_x1m, *p_xn2, *p_h;
    cudaGetSymbolAddress((void**)&p_xw,  g_xw);
    cudaGetSymbolAddress((void**)&p_qkv, g_qkv);
    cudaGetSymbolAddress((void**)&p_y,   g_y);
    cudaGetSymbolAddress((void**)&p_x1m, g_x1m);
    cudaGetSymbolAddress((void**)&p_xn2, g_xn2);
    cudaGetSymbolAddress((void**)&p_h,   g_h);

    // 1) LN1 + shift + window partition
    k_ln1_shift_win<<<MROWS, 256>>>(x1, n1g, n1b);

    // 2) QKV gemm: (50176,256) x (768,256)^T
    {
        dim3 grid(3 * CC / BN, MROWS / BM);
        k_gemm_nt<0><<<grid, 256>>>(p_xw, qkvw, qkvb, p_qkv,
                                    MROWS, 3 * CC, CC, nullptr, nullptr);
    }

    // 3) window attention
    k_attn<<<BW * NHD, 128>>>(rpb);

    // 4) proj gemm + window reverse + unshift + residual (+ tuple output y)
    {
        dim3 grid(CC / BN, MROWS / BM);
        k_gemm_nt<3><<<grid, 256>>>(p_y, projw, projb, p_x1m,
                                    MROWS, CC, CC, x1, out2);
    }

    // 5) LN2
    k_ln2<<<BB * LL, 256>>>(n2g, n2b);

    // 6) FC1 + GELU: (50176,256) x (1024,256)^T
    {
        dim3 grid(HID_ / BN, MROWS / BM);
        k_gemm_nt<1><<<grid, 256>>>(p_xn2, fc1w, fc1b, p_h,
                                    MROWS, HID_, CC, nullptr, nullptr);
    }

    // 7) FC2 + residual -> final output part 1
    {
        dim3 grid(CC / BN, MROWS / BM);
        k_gemm_nt<2><<<grid, 256>>>(p_h, fc2w, fc2b, out,
                                    MROWS, CC, HID_, p_x1m, nullptr);
    }
}

// round 9
// speedup vs baseline: 1.9377x; 1.9377x over previous
#include <cuda_runtime.h>
#include <cuda_fp16.h>
#include <math.h>

// ---------------- problem constants ----------------
#define BB   4
#define TT   4
#define HH   56
#define WW_  56
#define CC   256
#define NHD  8
#define HD   32
#define WS_  7
#define SS_  3
#define NTOK 49
#define HID_ 1024
#define GH   224
#define GW   56
#define NW   256
#define BW   1024
#define MROWS (BW*NTOK)         // 50176
#define LL   (TT*HH*WW_)        // 12544
#define BLC  (BB*LL*CC)         // 12845056

// ---------------- scratch ----------------
__device__ float g_xw  [MROWS * CC];
__device__ float g_qkv [MROWS * 3*CC];
__device__ float g_y   [MROWS * CC];
__device__ float g_x1m [BB*LL*CC];
__device__ float g_xn2 [BB*LL*CC];
__device__ float g_h   [BB*LL*HID_];

// ---------------- LN helpers ----------------
__device__ __forceinline__ void block_ln_stats(float v, float& mean, float& rstd) {
    float s = v, sq = v * v;
    #pragma unroll
    for (int o = 16; o; o >>= 1) {
        s  += __shfl_xor_sync(0xffffffffu, s,  o);
        sq += __shfl_xor_sync(0xffffffffu, sq, o);
    }
    __shared__ float s1[8], s2[8];
    int lane = threadIdx.x & 31, wid = threadIdx.x >> 5;
    if (lane == 0) { s1[wid] = s; s2[wid] = sq; }
    __syncthreads();
    float ts = 0.f, tq = 0.f;
    #pragma unroll
    for (int i = 0; i < 8; i++) { ts += s1[i]; tq += s2[i]; }
    mean = ts * (1.0f / CC);
    float var = tq * (1.0f / CC) - mean * mean;
    rstd = rsqrtf(var + 1e-5f);
}

__global__ __launch_bounds__(256) void k_ln1_shift_win(
    const float* __restrict__ x1, const float* __restrict__ g, const float* __restrict__ b)
{
    int row = blockIdx.x;
    int c = threadIdx.x;
    int bw = row / NTOK, n = row - bw * NTOK;
    int bat = bw >> 8, w = bw & 255;
    int hs = (w >> 3) * WS_ + n / WS_;
    int ws = (w & 7) * WS_ + n % WS_;
    int h0 = hs + SS_; if (h0 >= GH) h0 -= GH;
    int w0 = ws + SS_; if (w0 >= GW) w0 -= GW;
    const float* src = x1 + ((size_t)bat * LL + (size_t)h0 * GW + w0) * CC;
    float v = src[c];
    float m, rs; block_ln_stats(v, m, rs);
    g_xw[(size_t)row * CC + c] = (v - m) * rs * g[c] + b[c];
}

__global__ __launch_bounds__(256) void k_ln2(
    const float* __restrict__ g, const float* __restrict__ b)
{
    int row = blockIdx.x;
    int c = threadIdx.x;
    float v = g_x1m[(size_t)row * CC + c];
    float m, rs; block_ln_stats(v, m, rs);
    g_xn2[(size_t)row * CC + c] = (v - m) * rs * g[c] + b[c];
}

// ================= fp16 mma.sync GEMM =================
// C[M,Ntot] = A[M,K] @ Wt[Ntot,K]^T + bias.  Tile 128x128x32, 8 warps (4x2),
// warp tile 32x64, mma.m16n8k16, fp16 in / fp32 accumulate.
// EPI: 0 plain, 1 gelu(erf exact), 2 res-add, 3 proj scatter (+out2)
#define BM 128
#define BN 128
#define BK 32
#define PAD 40   // halves per smem row (stride 20 words -> conflict-free quads)

__device__ __forceinline__ void mma16816(float* c, const unsigned* a, unsigned b0, unsigned b1) {
    asm volatile("mma.sync.aligned.m16n8k16.row.col.f32.f16.f16.f32 "
                 "{%0,%1,%2,%3}, {%4,%5,%6,%7}, {%8,%9}, {%0,%1,%2,%3};"
                 : "+f"(c[0]), "+f"(c[1]), "+f"(c[2]), "+f"(c[3])
                 : "r"(a[0]), "r"(a[1]), "r"(a[2]), "r"(a[3]), "r"(b0), "r"(b1));
}

__device__ __forceinline__ void cvt_store16(__half* dst, const float4* v) {
    // 16 floats -> 16 halves, two 16B stores
    __half2 h0 = __floats2half2_rn(v[0].x, v[0].y);
    __half2 h1 = __floats2half2_rn(v[0].z, v[0].w);
    __half2 h2 = __floats2half2_rn(v[1].x, v[1].y);
    __half2 h3 = __floats2half2_rn(v[1].z, v[1].w);
    __half2 h4 = __floats2half2_rn(v[2].x, v[2].y);
    __half2 h5 = __floats2half2_rn(v[2].z, v[2].w);
    __half2 h6 = __floats2half2_rn(v[3].x, v[3].y);
    __half2 h7 = __floats2half2_rn(v[3].z, v[3].w);
    uint4 p0, p1;
    p0.x = *(unsigned*)&h0; p0.y = *(unsigned*)&h1; p0.z = *(unsigned*)&h2; p0.w = *(unsigned*)&h3;
    p1.x = *(unsigned*)&h4; p1.y = *(unsigned*)&h5; p1.z = *(unsigned*)&h6; p1.w = *(unsigned*)&h7;
    ((uint4*)dst)[0] = p0;
    ((uint4*)dst)[1] = p1;
}

template<int EPI>
__global__ __launch_bounds__(256) void k_gemm_mma(
    const float* __restrict__ A, const float* __restrict__ Wt,
    const float* __restrict__ bias, float* __restrict__ Cout,
    int Ntot, int K,
    const float* __restrict__ res, float* __restrict__ out2)
{
    __shared__ __half As[2][BM][PAD];
    __shared__ __half Bs[2][BN][PAD];

    int t = threadIdx.x, lane = t & 31, warp = t >> 5;
    int wm = (warp & 3) * 32, wn = (warp >> 2) * 64;
    int grp = lane >> 2, qid = lane & 3;
    int m0 = blockIdx.y * BM, n0 = blockIdx.x * BN;

    float acc[2][8][4];
    #pragma unroll
    for (int mt = 0; mt < 2; mt++)
        #pragma unroll
        for (int nt = 0; nt < 8; nt++)
            #pragma unroll
            for (int i = 0; i < 4; i++) acc[mt][nt][i] = 0.f;

    int lrow = t >> 1, lseg = (t & 1) * 16;
    const float* Ag = A  + (size_t)(m0 + lrow) * K + lseg;
    const float* Bg = Wt + (size_t)(n0 + lrow) * K + lseg;

    // prologue: stage 0
    {
        float4 av[4], bv[4];
        #pragma unroll
        for (int i = 0; i < 4; i++) { av[i] = ((const float4*)Ag)[i]; bv[i] = ((const float4*)Bg)[i]; }
        cvt_store16(&As[0][lrow][lseg], av);
        cvt_store16(&Bs[0][lrow][lseg], bv);
    }
    __syncthreads();

    int nk = K / BK;
    for (int ck = 0; ck < nk; ck++) {
        int buf = ck & 1;
        float4 av[4], bv[4];
        bool pf = (ck + 1 < nk);
        if (pf) {
            const float* ap = Ag + (ck + 1) * BK;
            const float* bp = Bg + (ck + 1) * BK;
            #pragma unroll
            for (int i = 0; i < 4; i++) { av[i] = ((const float4*)ap)[i]; bv[i] = ((const float4*)bp)[i]; }
        }
        #pragma unroll
        for (int ks = 0; ks < 2; ks++) {
            int kc = ks * 16 + qid * 2;
            unsigned a[2][4];
            #pragma unroll
            for (int mt = 0; mt < 2; mt++) {
                int r0 = wm + mt * 16 + grp;
                a[mt][0] = *(const unsigned*)&As[buf][r0    ][kc];
                a[mt][1] = *(const unsigned*)&As[buf][r0 + 8][kc];
                a[mt][2] = *(const unsigned*)&As[buf][r0    ][kc + 8];
                a[mt][3] = *(const unsigned*)&As[buf][r0 + 8][kc + 8];
            }
            #pragma unroll
            for (int nt = 0; nt < 8; nt++) {
                int rb = wn + nt * 8 + grp;
                unsigned b0 = *(const unsigned*)&Bs[buf][rb][kc];
                unsigned b1 = *(const unsigned*)&Bs[buf][rb][kc + 8];
                mma16816(acc[0][nt], a[0], b0, b1);
                mma16816(acc[1][nt], a[1], b0, b1);
            }
        }
        if (pf) {
            cvt_store16(&As[buf ^ 1][lrow][lseg], av);
            cvt_store16(&Bs[buf ^ 1][lrow][lseg], bv);
        }
        __syncthreads();
    }

    // epilogue: rows wm+mt*16+grp(+8), cols wn+nt*8+qid*2(+1)
    #pragma unroll
    for (int mt = 0; mt < 2; mt++) {
        #pragma unroll
        for (int half = 0; half < 2; half++) {
            int r = m0 + wm + mt * 16 + grp + half * 8;
            size_t dstrow = 0;
            if (EPI == 3) {
                int bw = r / NTOK, n = r - bw * NTOK;
                int bat = bw >> 8, w = bw & 255;
                int hs = (w >> 3) * WS_ + n / WS_;
                int ws = (w & 7) * WS_ + n % WS_;
                int h0 = hs + SS_; if (h0 >= GH) h0 -= GH;
                int w0 = ws + SS_; if (w0 >= GW) w0 -= GW;
                dstrow = ((size_t)bat * LL + (size_t)h0 * GW + w0) * CC;
            }
            #pragma unroll
            for (int nt = 0; nt < 8; nt++) {
                int c = n0 + wn + nt * 8 + qid * 2;
                float v0 = acc[mt][nt][half * 2 + 0] + bias[c];
                float v1 = acc[mt][nt][half * 2 + 1] + bias[c + 1];
                if (EPI == 0) {
                    *(float2*)(Cout + (size_t)r * Ntot + c) = make_float2(v0, v1);
                } else if (EPI == 1) {
                    v0 = 0.5f * v0 * (1.0f + erff(v0 * 0.70710678118654752f));
                    v1 = 0.5f * v1 * (1.0f + erff(v1 * 0.70710678118654752f));
                    *(float2*)(Cout + (size_t)r * Ntot + c) = make_float2(v0, v1);
                } else if (EPI == 2) {
                    float2 rr = *(const float2*)(res + (size_t)r * Ntot + c);
                    *(float2*)(Cout + (size_t)r * Ntot + c) = make_float2(rr.x + v0, rr.y + v1);
                } else {
                    size_t off = dstrow + c;
                    if (out2) *(float2*)(out2 + off) = make_float2(v0, v1);
                    float2 rr = *(const float2*)(res + off);
                    *(float2*)(Cout + off) = make_float2(rr.x + v0, rr.y + v1);
                }
            }
        }
    }
}

// ---------------- window attention (exact fp32) ----------------
__global__ __launch_bounds__(128) void k_attn(const float* __restrict__ rpb)
{
    int bw = blockIdx.x >> 3;
    int h  = blockIdx.x & 7;
    __shared__ float qs[NTOK][HD + 1];
    __shared__ float ks[NTOK][HD + 1];
    __shared__ float vs[NTOK][HD + 1];
    __shared__ float S [NTOK][NTOK + 3];
    __shared__ float bias_s[169];
    __shared__ int   reg_s[NTOK];
    int t = threadIdx.x;
    const float scale = 0.17677669529663687f;

    const float* base = g_qkv + (size_t)bw * NTOK * (3 * CC) + h * HD;
    for (int idx = t; idx < NTOK * HD; idx += 128) {
        int n = idx >> 5, d = idx & 31;
        const float* p = base + (size_t)n * (3 * CC);
        qs[n][d] = p[d] * scale;
        ks[n][d] = p[CC + d];
        vs[n][d] = p[2 * CC + d];
    }
    for (int idx = t; idx < 169; idx += 128) bias_s[idx] = rpb[idx * NHD + h];
    if (t < NTOK) {
        int w = bw & 255;
        int hs = (w >> 3) * WS_ + t / WS_;
        int ws = (w & 7) * WS_ + t % WS_;
        int rc = hs < (GH - WS_) ? 0 : (hs < (GH - SS_) ? 1 : 2);
        int cc = ws < (GW - WS_) ? 0 : (ws < (GW - SS_) ? 1 : 2);
        reg_s[t] = rc * 3 + cc;
    }
    __syncthreads();

    for (int idx = t; idx < NTOK * NTOK; idx += 128) {
        int i = idx / NTOK, j = idx - i * NTOK;
        float s = 0.f;
        #pragma unroll
        for (int d = 0; d < HD; d++) s = fmaf(qs[i][d], ks[j][d], s);
        int yi = i / 7, xi = i - yi * 7, yj = j / 7, xj = j - yj * 7;
        s += bias_s[(yi - yj + 6) * 13 + (xi - xj + 6)];
        if (reg_s[i] != reg_s[j]) s -= 100.f;
        S[i][j] = s;
    }
    __syncthreads();

    int wid = t >> 5, lane = t & 31;
    for (int i = wid; i < NTOK; i += 4) {
        float v0 = S[i][lane];
        float v1 = (lane < NTOK - 32) ? S[i][lane + 32] : -1e30f;
        float mx = fmaxf(v0, v1);
        #pragma unroll
        for (int o = 16; o; o >>= 1) mx = fmaxf(mx, __shfl_xor_sync(0xffffffffu, mx, o));
        float e0 = __expf(v0 - mx);
        float e1 = (lane < NTOK - 32) ? __expf(v1 - mx) : 0.f;
        float sm = e0 + e1;
        #pragma unroll
        for (int o = 16; o; o >>= 1) sm += __shfl_xor_sync(0xffffffffu, sm, o);
        float inv = 1.f / sm;
        S[i][lane] = e0 * inv;
        if (lane < NTOK - 32) S[i][lane + 32] = e1 * inv;
    }
    __syncthreads();

    float* yout = g_y + (size_t)bw * NTOK * CC + h * HD;
    for (int idx = t; idx < NTOK * HD; idx += 128) {
        int i = idx >> 5, d = idx & 31;
        float s = 0.f;
        #pragma unroll
        for (int j = 0; j < NTOK; j++) s = fmaf(S[i][j], vs[j][d], s);
        yout[(size_t)i * CC + d] = s;
    }
}

// ---------------- launch ----------------
extern "C" void kernel_launch(void* const* d_in, const int* in_sizes, int n_in,
                              void* d_out, int out_size)
{
    const float* x1    = (const float*)d_in[0];
    const float* n1g   = (const float*)d_in[2];
    const float* n1b   = (const float*)d_in[3];
    const float* qkvw  = (const float*)d_in[4];
    const float* qkvb  = (const float*)d_in[5];
    const float* projw = (const float*)d_in[6];
    const float* projb = (const float*)d_in[7];
    const float* rpb   = (const float*)d_in[8];
    const float* n2g   = (const float*)d_in[9];
    const float* n2b   = (const float*)d_in[10];
    const float* fc1w  = (const float*)d_in[11];
    const float* fc1b  = (const float*)d_in[12];
    const float* fc2w  = (const float*)d_in[13];
    const float* fc2b  = (const float*)d_in[14];
    float* out = (float*)d_out;
    float* out2 = (out_size >= 2 * BLC) ? out + BLC : nullptr;

    float *p_xw, *p_qkv, *p_y, *p_x1m, *p_xn2, *p_h;
    cudaGetSymbolAddress((void**)&p_xw,  g_xw);
    cudaGetSymbolAddress((void**)&p_qkv, g_qkv);
    cudaGetSymbolAddress((void**)&p_y,   g_y);
    cudaGetSymbolAddress((void**)&p_x1m, g_x1m);
    cudaGetSymbolAddress((void**)&p_xn2, g_xn2);
    cudaGetSymbolAddress((void**)&p_h,   g_h);

    // 1) LN1 + shift + window partition
    k_ln1_shift_win<<<MROWS, 256>>>(x1, n1g, n1b);

    // 2) QKV: (50176,256)x(768,256)^T
    k_gemm_mma<0><<<dim3(3 * CC / BN, MROWS / BM), 256>>>(
        p_xw, qkvw, qkvb, p_qkv, 3 * CC, CC, nullptr, nullptr);

    // 3) window attention
    k_attn<<<BW * NHD, 128>>>(rpb);

    // 4) proj + window reverse + unshift + residual (+ tuple out y)
    k_gemm_mma<3><<<dim3(CC / BN, MROWS / BM), 256>>>(
        p_y, projw, projb, p_x1m, CC, CC, x1, out2);

    // 5) LN2
    k_ln2<<<BB * LL, 256>>>(n2g, n2b);

    // 6) FC1 + GELU
    k_gemm_mma<1><<<dim3(HID_ / BN, MROWS / BM), 256>>>(
        p_xn2, fc1w, fc1b, p_h, HID_, CC, nullptr, nullptr);

    // 7) FC2 + residual -> final
    k_gemm_mma<2><<<dim3(CC / BN, MROWS / BM), 256>>>(
        p_h, fc2w, fc2b, out, CC, HID_, p_x1m, nullptr);
}

// round 10
// speedup vs baseline: 3.2849x; 1.6953x over previous
#include <cuda_runtime.h>
#include <cuda_fp16.h>
#include <math.h>

// ---------------- problem constants ----------------
#define BB   4
#define TT   4
#define HH   56
#define WW_  56
#define CC   256
#define NHD  8
#define HD   32
#define WS_  7
#define SS_  3
#define NTOK 49
#define HID_ 1024
#define GH   224
#define GW   56
#define NW   256
#define BW   1024
#define MROWS (BW*NTOK)         // 50176
#define LL   (TT*HH*WW_)        // 12544
#define BLC  (BB*LL*CC)         // 12845056

// ---------------- scratch (fp16 activations, fp32 residual) ----------------
__device__ __align__(16) __half g_xw_h [MROWS * CC];      // LN1+shift+win (half)
__device__ __align__(16) __half g_qkv_h[MROWS * 3*CC];    // qkv (half)
__device__ __align__(16) __half g_y_h  [MROWS * CC];      // attn out (half)
__device__ float g_x1m [BB*LL*CC];                        // x1 + attnproj (fp32)
__device__ __align__(16) __half g_xn2_h[BB*LL*CC];        // LN2 out (half)
__device__ __align__(16) __half g_h_h  [BB*LL*HID_];      // mlp hidden (half)
// fp16 weights
__device__ __align__(16) __half g_wqkv[3*CC*CC];
__device__ __align__(16) __half g_wproj[CC*CC];
__device__ __align__(16) __half g_wfc1[HID_*CC];
__device__ __align__(16) __half g_wfc2[CC*HID_];

// ---------------- fp32 -> fp16 convert (weights) ----------------
__global__ __launch_bounds__(256) void k_f2h(const float* __restrict__ src,
                                             __half* __restrict__ dst, int n4)
{
    int i = blockIdx.x * 256 + threadIdx.x;
    if (i < n4) {
        float4 v = ((const float4*)src)[i];
        __half2 a = __floats2half2_rn(v.x, v.y);
        __half2 b = __floats2half2_rn(v.z, v.w);
        ((__half2*)dst)[2 * i]     = a;
        ((__half2*)dst)[2 * i + 1] = b;
    }
}

// ---------------- LN helpers ----------------
__device__ __forceinline__ void block_ln_stats(float v, float& mean, float& rstd) {
    float s = v, sq = v * v;
    #pragma unroll
    for (int o = 16; o; o >>= 1) {
        s  += __shfl_xor_sync(0xffffffffu, s,  o);
        sq += __shfl_xor_sync(0xffffffffu, sq, o);
    }
    __shared__ float s1[8], s2[8];
    int lane = threadIdx.x & 31, wid = threadIdx.x >> 5;
    if (lane == 0) { s1[wid] = s; s2[wid] = sq; }
    __syncthreads();
    float ts = 0.f, tq = 0.f;
    #pragma unroll
    for (int i = 0; i < 8; i++) { ts += s1[i]; tq += s2[i]; }
    mean = ts * (1.0f / CC);
    float var = tq * (1.0f / CC) - mean * mean;
    rstd = rsqrtf(var + 1e-5f);
}

// LN1 + cyclic shift + window partition -> half
__global__ __launch_bounds__(256) void k_ln1_shift_win(
    const float* __restrict__ x1, const float* __restrict__ g, const float* __restrict__ b)
{
    int row = blockIdx.x;
    int c = threadIdx.x;
    int bw = row / NTOK, n = row - bw * NTOK;
    int bat = bw >> 8, w = bw & 255;
    int hs = (w >> 3) * WS_ + n / WS_;
    int ws = (w & 7) * WS_ + n % WS_;
    int h0 = hs + SS_; if (h0 >= GH) h0 -= GH;
    int w0 = ws + SS_; if (w0 >= GW) w0 -= GW;
    const float* src = x1 + ((size_t)bat * LL + (size_t)h0 * GW + w0) * CC;
    float v = src[c];
    float m, rs; block_ln_stats(v, m, rs);
    g_xw_h[(size_t)row * CC + c] = __float2half((v - m) * rs * g[c] + b[c]);
}

// LN2: fp32 in (g_x1m) -> half out (g_xn2_h)
__global__ __launch_bounds__(256) void k_ln2(
    const float* __restrict__ g, const float* __restrict__ b)
{
    int row = blockIdx.x;
    int c = threadIdx.x;
    float v = g_x1m[(size_t)row * CC + c];
    float m, rs; block_ln_stats(v, m, rs);
    g_xn2_h[(size_t)row * CC + c] = __float2half((v - m) * rs * g[c] + b[c]);
}

// ================= fp16 mma.sync GEMM, cp.async double-buffered =================
// C[M,Ntot] = A[M,K]h @ Wt[Ntot,K]h^T + bias.  128x128x32 tile, 8 warps, 32x64/warp.
// EPI: 0 plain->half, 1 gelu->half, 2 res-add->fp32, 3 proj scatter->fp32 (+out2 fp32)
#define BM 128
#define BN 128
#define BK 32
#define PAD 40

__device__ __forceinline__ unsigned smem_u32(const void* p) {
    unsigned a;
    asm("{ .reg .u64 t; cvta.to.shared.u64 t, %1; cvt.u32.u64 %0, t; }" : "=r"(a) : "l"(p));
    return a;
}
__device__ __forceinline__ void cp16(unsigned dst, const void* src) {
    asm volatile("cp.async.cg.shared.global [%0], [%1], 16;" :: "r"(dst), "l"(src));
}
#define CP_COMMIT() asm volatile("cp.async.commit_group;" ::: "memory")

__device__ __forceinline__ void mma16816(float* c, const unsigned* a, unsigned b0, unsigned b1) {
    asm volatile("mma.sync.aligned.m16n8k16.row.col.f32.f16.f16.f32 "
                 "{%0,%1,%2,%3}, {%4,%5,%6,%7}, {%8,%9}, {%0,%1,%2,%3};"
                 : "+f"(c[0]), "+f"(c[1]), "+f"(c[2]), "+f"(c[3])
                 : "r"(a[0]), "r"(a[1]), "r"(a[2]), "r"(a[3]), "r"(b0), "r"(b1));
}

template<int EPI>
__global__ __launch_bounds__(256, 2) void k_gemm_h(
    const __half* __restrict__ A, const __half* __restrict__ Wt,
    const float* __restrict__ bias, void* __restrict__ CoutV,
    int Ntot, int K,
    const float* __restrict__ res, float* __restrict__ out2)
{
    __shared__ __half As[2][BM][PAD];
    __shared__ __half Bs[2][BN][PAD];

    int t = threadIdx.x, lane = t & 31, warp = t >> 5;
    int wm = (warp & 3) * 32, wn = (warp >> 2) * 64;
    int grp = lane >> 2, qid = lane & 3;
    int m0 = blockIdx.y * BM, n0 = blockIdx.x * BN;

    float acc[2][8][4];
    #pragma unroll
    for (int mt = 0; mt < 2; mt++)
        #pragma unroll
        for (int nt = 0; nt < 8; nt++)
            #pragma unroll
            for (int i = 0; i < 4; i++) acc[mt][nt][i] = 0.f;

    // loader: 512 16B-chunks per tile (128 rows x 4 segs); thread t -> chunks t, t+256
    int r0 = t >> 2, s0 = (t & 3) * 8;
    int r1 = (t + 256) >> 2, s1 = ((t + 256) & 3) * 8;
    const __half* Agr0 = A  + (size_t)(m0 + r0) * K + s0;
    const __half* Agr1 = A  + (size_t)(m0 + r1) * K + s1;
    const __half* Bgr0 = Wt + (size_t)(n0 + r0) * K + s0;
    const __half* Bgr1 = Wt + (size_t)(n0 + r1) * K + s1;

    // prologue: stage 0
    cp16(smem_u32(&As[0][r0][s0]), Agr0);
    cp16(smem_u32(&As[0][r1][s1]), Agr1);
    cp16(smem_u32(&Bs[0][r0][s0]), Bgr0);
    cp16(smem_u32(&Bs[0][r1][s1]), Bgr1);
    CP_COMMIT();

    int nk = K / BK;
    for (int ck = 0; ck < nk; ck++) {
        int buf = ck & 1;
        if (ck + 1 < nk) {
            int k1 = (ck + 1) * BK;
            cp16(smem_u32(&As[buf ^ 1][r0][s0]), Agr0 + k1);
            cp16(smem_u32(&As[buf ^ 1][r1][s1]), Agr1 + k1);
            cp16(smem_u32(&Bs[buf ^ 1][r0][s0]), Bgr0 + k1);
            cp16(smem_u32(&Bs[buf ^ 1][r1][s1]), Bgr1 + k1);
            CP_COMMIT();
            asm volatile("cp.async.wait_group 1;" ::: "memory");
        } else {
            asm volatile("cp.async.wait_group 0;" ::: "memory");
        }
        __syncthreads();

        #pragma unroll
        for (int ks = 0; ks < 2; ks++) {
            int kc = ks * 16 + qid * 2;
            unsigned a[2][4];
            #pragma unroll
            for (int mt = 0; mt < 2; mt++) {
                int ra = wm + mt * 16 + grp;
                a[mt][0] = *(const unsigned*)&As[buf][ra    ][kc];
                a[mt][1] = *(const unsigned*)&As[buf][ra + 8][kc];
                a[mt][2] = *(const unsigned*)&As[buf][ra    ][kc + 8];
                a[mt][3] = *(const unsigned*)&As[buf][ra + 8][kc + 8];
            }
            #pragma unroll
            for (int nt = 0; nt < 8; nt++) {
                int rb = wn + nt * 8 + grp;
                unsigned b0 = *(const unsigned*)&Bs[buf][rb][kc];
                unsigned b1 = *(const unsigned*)&Bs[buf][rb][kc + 8];
                mma16816(acc[0][nt], a[0], b0, b1);
                mma16816(acc[1][nt], a[1], b0, b1);
            }
        }
        __syncthreads();
    }

    // epilogue: rows wm+mt*16+grp(+8), cols wn+nt*8+qid*2(+1)
    #pragma unroll
    for (int mt = 0; mt < 2; mt++) {
        #pragma unroll
        for (int half = 0; half < 2; half++) {
            int r = m0 + wm + mt * 16 + grp + half * 8;
            size_t dstrow = 0;
            if (EPI == 3) {
                int bw = r / NTOK, n = r - bw * NTOK;
                int bat = bw >> 8, w = bw & 255;
                int hs = (w >> 3) * WS_ + n / WS_;
                int ws = (w & 7) * WS_ + n % WS_;
                int h0 = hs + SS_; if (h0 >= GH) h0 -= GH;
                int w0 = ws + SS_; if (w0 >= GW) w0 -= GW;
                dstrow = ((size_t)bat * LL + (size_t)h0 * GW + w0) * CC;
            }
            #pragma unroll
            for (int nt = 0; nt < 8; nt++) {
                int c = n0 + wn + nt * 8 + qid * 2;
                float v0 = acc[mt][nt][half * 2 + 0] + bias[c];
                float v1 = acc[mt][nt][half * 2 + 1] + bias[c + 1];
                if (EPI == 0) {
                    *(__half2*)((__half*)CoutV + (size_t)r * Ntot + c) = __floats2half2_rn(v0, v1);
                } else if (EPI == 1) {
                    v0 = 0.5f * v0 * (1.0f + erff(v0 * 0.70710678118654752f));
                    v1 = 0.5f * v1 * (1.0f + erff(v1 * 0.70710678118654752f));
                    *(__half2*)((__half*)CoutV + (size_t)r * Ntot + c) = __floats2half2_rn(v0, v1);
                } else if (EPI == 2) {
                    float* Cout = (float*)CoutV;
                    float2 rr = *(const float2*)(res + (size_t)r * Ntot + c);
                    *(float2*)(Cout + (size_t)r * Ntot + c) = make_float2(rr.x + v0, rr.y + v1);
                } else {
                    float* Cout = (float*)CoutV;
                    size_t off = dstrow + c;
                    if (out2) *(float2*)(out2 + off) = make_float2(v0, v1);
                    float2 rr = *(const float2*)(res + off);
                    *(float2*)(Cout + off) = make_float2(rr.x + v0, rr.y + v1);
                }
            }
        }
    }
}

// ---------------- window attention (fp32 math, fp16 I/O) ----------------
__global__ __launch_bounds__(128) void k_attn(const float* __restrict__ rpb)
{
    int bw = blockIdx.x >> 3;
    int h  = blockIdx.x & 7;
    __shared__ float qs[NTOK][HD + 1];
    __shared__ float ks[NTOK][HD + 1];
    __shared__ float vs[NTOK][HD + 1];
    __shared__ float S [NTOK][NTOK + 3];
    __shared__ float bias_s[169];
    __shared__ int   reg_s[NTOK];
    int t = threadIdx.x;
    const float scale = 0.17677669529663687f;

    const __half* base = g_qkv_h + (size_t)bw * NTOK * (3 * CC) + h * HD;
    for (int idx = t; idx < NTOK * HD; idx += 128) {
        int n = idx >> 5, d = idx & 31;
        const __half* p = base + (size_t)n * (3 * CC);
        qs[n][d] = __half2float(p[d]) * scale;
        ks[n][d] = __half2float(p[CC + d]);
        vs[n][d] = __half2float(p[2 * CC + d]);
    }
    for (int idx = t; idx < 169; idx += 128) bias_s[idx] = rpb[idx * NHD + h];
    if (t < NTOK) {
        int w = bw & 255;
        int hs = (w >> 3) * WS_ + t / WS_;
        int ws = (w & 7) * WS_ + t % WS_;
        int rc = hs < (GH - WS_) ? 0 : (hs < (GH - SS_) ? 1 : 2);
        int cc = ws < (GW - WS_) ? 0 : (ws < (GW - SS_) ? 1 : 2);
        reg_s[t] = rc * 3 + cc;
    }
    __syncthreads();

    for (int idx = t; idx < NTOK * NTOK; idx += 128) {
        int i = idx / NTOK, j = idx - i * NTOK;
        float s = 0.f;
        #pragma unroll
        for (int d = 0; d < HD; d++) s = fmaf(qs[i][d], ks[j][d], s);
        int yi = i / 7, xi = i - yi * 7, yj = j / 7, xj = j - yj * 7;
        s += bias_s[(yi - yj + 6) * 13 + (xi - xj + 6)];
        if (reg_s[i] != reg_s[j]) s -= 100.f;
        S[i][j] = s;
    }
    __syncthreads();

    int wid = t >> 5, lane = t & 31;
    for (int i = wid; i < NTOK; i += 4) {
        float v0 = S[i][lane];
        float v1 = (lane < NTOK - 32) ? S[i][lane + 32] : -1e30f;
        float mx = fmaxf(v0, v1);
        #pragma unroll
        for (int o = 16; o; o >>= 1) mx = fmaxf(mx, __shfl_xor_sync(0xffffffffu, mx, o));
        float e0 = __expf(v0 - mx);
        float e1 = (lane < NTOK - 32) ? __expf(v1 - mx) : 0.f;
        float sm = e0 + e1;
        #pragma unroll
        for (int o = 16; o; o >>= 1) sm += __shfl_xor_sync(0xffffffffu, sm, o);
        float inv = 1.f / sm;
        S[i][lane] = e0 * inv;
        if (lane < NTOK - 32) S[i][lane + 32] = e1 * inv;
    }
    __syncthreads();

    __half* yout = g_y_h + (size_t)bw * NTOK * CC + h * HD;
    for (int idx = t; idx < NTOK * HD; idx += 128) {
        int i = idx >> 5, d = idx & 31;
        float s = 0.f;
        #pragma unroll
        for (int j = 0; j < NTOK; j++) s = fmaf(S[i][j], vs[j][d], s);
        yout[(size_t)i * CC + d] = __float2half(s);
    }
}

// ---------------- launch ----------------
extern "C" void kernel_launch(void* const* d_in, const int* in_sizes, int n_in,
                              void* d_out, int out_size)
{
    const float* x1    = (const float*)d_in[0];
    const float* n1g   = (const float*)d_in[2];
    const float* n1b   = (const float*)d_in[3];
    const float* qkvw  = (const float*)d_in[4];
    const float* qkvb  = (const float*)d_in[5];
    const float* projw = (const float*)d_in[6];
    const float* projb = (const float*)d_in[7];
    const float* rpb   = (const float*)d_in[8];
    const float* n2g   = (const float*)d_in[9];
    const float* n2b   = (const float*)d_in[10];
    const float* fc1w  = (const float*)d_in[11];
    const float* fc1b  = (const float*)d_in[12];
    const float* fc2w  = (const float*)d_in[13];
    const float* fc2b  = (const float*)d_in[14];
    float* out = (float*)d_out;
    float* out2 = (out_size >= 2 * BLC) ? out + BLC : nullptr;

    __half *p_xw, *p_qkv, *p_y, *p_xn2, *p_h;
    __half *p_wqkv, *p_wproj, *p_wfc1, *p_wfc2;
    float *p_x1m;
    cudaGetSymbolAddress((void**)&p_xw,   g_xw_h);
    cudaGetSymbolAddress((void**)&p_qkv,  g_qkv_h);
    cudaGetSymbolAddress((void**)&p_y,    g_y_h);
    cudaGetSymbolAddress((void**)&p_x1m,  g_x1m);
    cudaGetSymbolAddress((void**)&p_xn2,  g_xn2_h);
    cudaGetSymbolAddress((void**)&p_h,    g_h_h);
    cudaGetSymbolAddress((void**)&p_wqkv, g_wqkv);
    cudaGetSymbolAddress((void**)&p_wproj,g_wproj);
    cudaGetSymbolAddress((void**)&p_wfc1, g_wfc1);
    cudaGetSymbolAddress((void**)&p_wfc2, g_wfc2);

    // 0) weights fp32 -> fp16
    k_f2h<<<(3 * CC * CC / 4 + 255) / 256, 256>>>(qkvw,  p_wqkv, 3 * CC * CC / 4);
    k_f2h<<<(CC * CC / 4 + 255) / 256, 256>>>(projw, p_wproj, CC * CC / 4);
    k_f2h<<<(HID_ * CC / 4 + 255) / 256, 256>>>(fc1w,  p_wfc1, HID_ * CC / 4);
    k_f2h<<<(CC * HID_ / 4 + 255) / 256, 256>>>(fc2w,  p_wfc2, CC * HID_ / 4);

    // 1) LN1 + shift + window partition (half out)
    k_ln1_shift_win<<<MROWS, 256>>>(x1, n1g, n1b);

    // 2) QKV
    k_gemm_h<0><<<dim3(3 * CC / BN, MROWS / BM), 256>>>(
        p_xw, p_wqkv, qkvb, p_qkv, 3 * CC, CC, nullptr, nullptr);

    // 3) window attention
    k_attn<<<BW * NHD, 128>>>(rpb);

    // 4) proj + window reverse + unshift + residual (+ tuple out y)
    k_gemm_h<3><<<dim3(CC / BN, MROWS / BM), 256>>>(
        p_y, p_wproj, projb, p_x1m, CC, CC, x1, out2);

    // 5) LN2 (half out)
    k_ln2<<<BB * LL, 256>>>(n2g, n2b);

    // 6) FC1 + GELU (half out)
    k_gemm_h<1><<<dim3(HID_ / BN, MROWS / BM), 256>>>(
        p_xn2, p_wfc1, fc1b, p_h, HID_, CC, nullptr, nullptr);

    // 7) FC2 + residual -> final (fp32)
    k_gemm_h<2><<<dim3(CC / BN, MROWS / BM), 256>>>(
        p_h, p_wfc2, fc2b, out, CC, HID_, p_x1m, nullptr);
}

// round 11
// speedup vs baseline: 3.5954x; 1.0945x over previous
#include <cuda_runtime.h>
#include <cuda_fp16.h>
#include <math.h>

// ---------------- problem constants ----------------
#define BB   4
#define TT   4
#define HH   56
#define WW_  56
#define CC   256
#define NHD  8
#define HD   32
#define WS_  7
#define SS_  3
#define NTOK 49
#define HID_ 1024
#define GH   224
#define GW   56
#define NW   256
#define BW   1024
#define MROWS (BW*NTOK)         // 50176
#define LL   (TT*HH*WW_)        // 12544
#define BLC  (BB*LL*CC)         // 12845056

// ---------------- scratch ----------------
__device__ __align__(16) __half g_xw_h [MROWS * CC];
__device__ __align__(16) __half g_qkv_h[MROWS * 3*CC];
__device__ __align__(16) __half g_y_h  [MROWS * CC];
__device__ float g_x1m [BB*LL*CC];
__device__ __align__(16) __half g_xn2_h[BB*LL*CC];
__device__ __align__(16) __half g_h_h  [BB*LL*HID_];
__device__ __align__(16) __half g_wqkv[3*CC*CC];
__device__ __align__(16) __half g_wproj[CC*CC];
__device__ __align__(16) __half g_wfc1[HID_*CC];
__device__ __align__(16) __half g_wfc2[CC*HID_];

// ---------------- fused weight convert (all four) ----------------
#define NQ_QKV (3*CC*CC/4)     // 49152 quads
#define NQ_PROJ (CC*CC/4)      // 16384
#define NQ_FC1 (HID_*CC/4)     // 65536
#define NQ_FC2 (CC*HID_/4)     // 65536
#define NQ_TOT (NQ_QKV+NQ_PROJ+NQ_FC1+NQ_FC2)

__global__ __launch_bounds__(256) void k_f2h_all(
    const float* __restrict__ qkvw, const float* __restrict__ projw,
    const float* __restrict__ fc1w, const float* __restrict__ fc2w,
    __half* __restrict__ dqkv, __half* __restrict__ dproj,
    __half* __restrict__ dfc1, __half* __restrict__ dfc2)
{
    int i = blockIdx.x * 256 + threadIdx.x;
    if (i >= NQ_TOT) return;
    const float* src; __half* dst; int j = i;
    if (j < NQ_QKV)                 { src = qkvw; dst = dqkv; }
    else if ((j -= NQ_QKV) < NQ_PROJ) { src = projw; dst = dproj; }
    else if ((j -= NQ_PROJ) < NQ_FC1) { src = fc1w; dst = dfc1; }
    else { j -= NQ_FC1; src = fc2w; dst = dfc2; }
    float4 v = ((const float4*)src)[j];
    ((__half2*)dst)[2 * j]     = __floats2half2_rn(v.x, v.y);
    ((__half2*)dst)[2 * j + 1] = __floats2half2_rn(v.z, v.w);
}

// ---------------- LN helpers ----------------
__device__ __forceinline__ void block_ln_stats(float v, float& mean, float& rstd) {
    float s = v, sq = v * v;
    #pragma unroll
    for (int o = 16; o; o >>= 1) {
        s  += __shfl_xor_sync(0xffffffffu, s,  o);
        sq += __shfl_xor_sync(0xffffffffu, sq, o);
    }
    __shared__ float s1[8], s2[8];
    int lane = threadIdx.x & 31, wid = threadIdx.x >> 5;
    if (lane == 0) { s1[wid] = s; s2[wid] = sq; }
    __syncthreads();
    float ts = 0.f, tq = 0.f;
    #pragma unroll
    for (int i = 0; i < 8; i++) { ts += s1[i]; tq += s2[i]; }
    mean = ts * (1.0f / CC);
    float var = tq * (1.0f / CC) - mean * mean;
    rstd = rsqrtf(var + 1e-5f);
}

__global__ __launch_bounds__(256) void k_ln1_shift_win(
    const float* __restrict__ x1, const float* __restrict__ g, const float* __restrict__ b)
{
    int row = blockIdx.x;
    int c = threadIdx.x;
    int bw = row / NTOK, n = row - bw * NTOK;
    int bat = bw >> 8, w = bw & 255;
    int hs = (w >> 3) * WS_ + n / WS_;
    int ws = (w & 7) * WS_ + n % WS_;
    int h0 = hs + SS_; if (h0 >= GH) h0 -= GH;
    int w0 = ws + SS_; if (w0 >= GW) w0 -= GW;
    const float* src = x1 + ((size_t)bat * LL + (size_t)h0 * GW + w0) * CC;
    float v = src[c];
    float m, rs; block_ln_stats(v, m, rs);
    g_xw_h[(size_t)row * CC + c] = __float2half((v - m) * rs * g[c] + b[c]);
}

__global__ __launch_bounds__(256) void k_ln2(
    const float* __restrict__ g, const float* __restrict__ b)
{
    int row = blockIdx.x;
    int c = threadIdx.x;
    float v = g_x1m[(size_t)row * CC + c];
    float m, rs; block_ln_stats(v, m, rs);
    g_xn2_h[(size_t)row * CC + c] = __float2half((v - m) * rs * g[c] + b[c]);
}

// ================= fp16 mma GEMM: ldmatrix + BK=64 + cp.async 2-stage =================
#define BM 128
#define BN 128
#define BK 64
#define SROW 72                       // halves per smem row (36 words: conflict-free)
#define MAT_H (BM * SROW)             // 9216 halves per matrix
#define STAGE_B (2 * MAT_H * 2)       // bytes per stage (A+B) = 36864
#define GEMM_SMEM (2 * STAGE_B)       // 73728

__device__ __forceinline__ unsigned smem_u32(const void* p) {
    unsigned a;
    asm("{ .reg .u64 t; cvta.to.shared.u64 t, %1; cvt.u32.u64 %0, t; }" : "=r"(a) : "l"(p));
    return a;
}
__device__ __forceinline__ void cp16(unsigned dst, const void* src) {
    asm volatile("cp.async.cg.shared.global [%0], [%1], 16;" :: "r"(dst), "l"(src));
}
#define CP_COMMIT() asm volatile("cp.async.commit_group;" ::: "memory")

__device__ __forceinline__ void mma16816(float* c, const unsigned* a, unsigned b0, unsigned b1) {
    asm volatile("mma.sync.aligned.m16n8k16.row.col.f32.f16.f16.f32 "
                 "{%0,%1,%2,%3}, {%4,%5,%6,%7}, {%8,%9}, {%0,%1,%2,%3};"
                 : "+f"(c[0]), "+f"(c[1]), "+f"(c[2]), "+f"(c[3])
                 : "r"(a[0]), "r"(a[1]), "r"(a[2]), "r"(a[3]), "r"(b0), "r"(b1));
}
__device__ __forceinline__ void ldsm4(unsigned* r, unsigned addr) {
    asm volatile("ldmatrix.sync.aligned.m8n8.x4.shared.b16 {%0,%1,%2,%3}, [%4];"
                 : "=r"(r[0]), "=r"(r[1]), "=r"(r[2]), "=r"(r[3]) : "r"(addr));
}

// EPI: 0 plain->half, 1 gelu->half, 2 res-add->fp32, 3 proj scatter->fp32 (+out2)
template<int EPI>
__global__ __launch_bounds__(256, 2) void k_gemm_h(
    const __half* __restrict__ A, const __half* __restrict__ Wt,
    const float* __restrict__ bias, void* __restrict__ CoutV,
    int Ntot, int K,
    const float* __restrict__ res, float* __restrict__ out2)
{
    extern __shared__ __half dsm[];
    unsigned sA = smem_u32(dsm);                 // stage0 A
    unsigned sB = sA + MAT_H * 2;                // stage0 B

    int t = threadIdx.x, lane = t & 31, warp = t >> 5;
    int wm = (warp & 3) * 32, wn = (warp >> 2) * 64;
    int grp = lane >> 2, qid = lane & 3;
    int m0 = blockIdx.y * BM, n0 = blockIdx.x * BN;

    float acc[2][8][4];
    #pragma unroll
    for (int mt = 0; mt < 2; mt++)
        #pragma unroll
        for (int nt = 0; nt < 8; nt++)
            #pragma unroll
            for (int i = 0; i < 4; i++) acc[mt][nt][i] = 0.f;

    // loader: 1024 16B chunks per matrix; thread t handles rows (t>>3)+32i, seg t&7
    int lrow = t >> 3, lseg = t & 7;
    const __half* Ap = A  + (size_t)(m0 + lrow) * K + lseg * 8;
    const __half* Bp = Wt + (size_t)(n0 + lrow) * K + lseg * 8;
    unsigned dA = sA + (lrow * SROW + lseg * 8) * 2;
    unsigned dB = sB + (lrow * SROW + lseg * 8) * 2;
    const unsigned dstep = 32 * SROW * 2;        // 32 rows in bytes

    // ldmatrix per-lane offsets (halves)
    int ar = (lane & 7) + ((lane >> 3) & 1) * 8, ac = (lane >> 4) * 8;
    int aoff = (wm + ar) * SROW + ac;
    int br = (lane & 7) + (lane >> 4) * 8, bc = ((lane >> 3) & 1) * 8;
    int boff = (wn + br) * SROW + bc;

    // prologue: stage 0
    #pragma unroll
    for (int i = 0; i < 4; i++) {
        cp16(dA + i * dstep, Ap + (size_t)(32 * i) * K);
        cp16(dB + i * dstep, Bp + (size_t)(32 * i) * K);
    }
    CP_COMMIT();

    int nk = K / BK;
    for (int ck = 0; ck < nk; ck++) {
        unsigned stg = (ck & 1) ? STAGE_B : 0;
        if (ck + 1 < nk) {
            unsigned stg1 = ((ck + 1) & 1) ? STAGE_B : 0;
            int k1 = (ck + 1) * BK;
            #pragma unroll
            for (int i = 0; i < 4; i++) {
                cp16(dA + stg1 + i * dstep, Ap + (size_t)(32 * i) * K + k1);
                cp16(dB + stg1 + i * dstep, Bp + (size_t)(32 * i) * K + k1);
            }
            CP_COMMIT();
            asm volatile("cp.async.wait_group 1;" ::: "memory");
        } else {
            asm volatile("cp.async.wait_group 0;" ::: "memory");
        }
        __syncthreads();

        unsigned aA = sA + stg, aB = sB + stg;
        #pragma unroll
        for (int ks = 0; ks < 4; ks++) {
            unsigned a[2][4];
            ldsm4(a[0], aA + (aoff + ks * 16) * 2);
            ldsm4(a[1], aA + (aoff + 16 * SROW + ks * 16) * 2);
            #pragma unroll
            for (int np = 0; np < 4; np++) {
                unsigned bf[4];
                ldsm4(bf, aB + (boff + np * 16 * SROW + ks * 16) * 2);
                mma16816(acc[0][np * 2    ], a[0], bf[0], bf[1]);
                mma16816(acc[0][np * 2 + 1], a[0], bf[2], bf[3]);
                mma16816(acc[1][np * 2    ], a[1], bf[0], bf[1]);
                mma16816(acc[1][np * 2 + 1], a[1], bf[2], bf[3]);
            }
        }
        __syncthreads();
    }

    // epilogue: rows wm+mt*16+grp(+8), cols wn+nt*8+qid*2(+1)
    #pragma unroll
    for (int mt = 0; mt < 2; mt++) {
        #pragma unroll
        for (int half = 0; half < 2; half++) {
            int r = m0 + wm + mt * 16 + grp + half * 8;
            size_t dstrow = 0;
            if (EPI == 3) {
                int bw = r / NTOK, n = r - bw * NTOK;
                int bat = bw >> 8, w = bw & 255;
                int hs = (w >> 3) * WS_ + n / WS_;
                int ws = (w & 7) * WS_ + n % WS_;
                int h0 = hs + SS_; if (h0 >= GH) h0 -= GH;
                int w0 = ws + SS_; if (w0 >= GW) w0 -= GW;
                dstrow = ((size_t)bat * LL + (size_t)h0 * GW + w0) * CC;
            }
            #pragma unroll
            for (int nt = 0; nt < 8; nt++) {
                int c = n0 + wn + nt * 8 + qid * 2;
                float v0 = acc[mt][nt][half * 2 + 0] + bias[c];
                float v1 = acc[mt][nt][half * 2 + 1] + bias[c + 1];
                if (EPI == 0) {
                    *(__half2*)((__half*)CoutV + (size_t)r * Ntot + c) = __floats2half2_rn(v0, v1);
                } else if (EPI == 1) {
                    v0 = 0.5f * v0 * (1.0f + erff(v0 * 0.70710678118654752f));
                    v1 = 0.5f * v1 * (1.0f + erff(v1 * 0.70710678118654752f));
                    *(__half2*)((__half*)CoutV + (size_t)r * Ntot + c) = __floats2half2_rn(v0, v1);
                } else if (EPI == 2) {
                    float* Cout = (float*)CoutV;
                    float2 rr = *(const float2*)(res + (size_t)r * Ntot + c);
                    *(float2*)(Cout + (size_t)r * Ntot + c) = make_float2(rr.x + v0, rr.y + v1);
                } else {
                    float* Cout = (float*)CoutV;
                    size_t off = dstrow + c;
                    if (out2) *(float2*)(out2 + off) = make_float2(v0, v1);
                    float2 rr = *(const float2*)(res + off);
                    *(float2*)(Cout + off) = make_float2(rr.x + v0, rr.y + v1);
                }
            }
        }
    }
}

// ---------------- window attention (fp32 math, fp16 I/O, vectorized loads) ----------------
__global__ __launch_bounds__(128) void k_attn(const float* __restrict__ rpb)
{
    int bw = blockIdx.x >> 3;
    int h  = blockIdx.x & 7;
    __shared__ float qs[NTOK][HD + 1];
    __shared__ float ks[NTOK][HD + 1];
    __shared__ float vs[NTOK][HD + 1];
    __shared__ float S [NTOK][NTOK + 3];
    __shared__ float bias_s[169];
    __shared__ int   reg_s[NTOK];
    int t = threadIdx.x;
    const float scale = 0.17677669529663687f;

    const __half* base = g_qkv_h + (size_t)bw * NTOK * (3 * CC) + h * HD;
    // 3 matrices x 49 rows x 4 seg(8 halves) = 588 uint4 chunks
    for (int idx = t; idx < 3 * NTOK * 4; idx += 128) {
        int mat = idx / (NTOK * 4), ch = idx - mat * NTOK * 4;
        int n = ch >> 2, seg = ch & 3;
        uint4 u = *(const uint4*)(base + (size_t)n * (3 * CC) + mat * CC + seg * 8);
        float2 f0 = __half22float2(*(__half2*)&u.x);
        float2 f1 = __half22float2(*(__half2*)&u.y);
        float2 f2 = __half22float2(*(__half2*)&u.z);
        float2 f3 = __half22float2(*(__half2*)&u.w);
        float* dst = (mat == 0 ? &qs[n][seg * 8] : mat == 1 ? &ks[n][seg * 8] : &vs[n][seg * 8]);
        if (mat == 0) {
            dst[0] = f0.x * scale; dst[1] = f0.y * scale;
            dst[2] = f1.x * scale; dst[3] = f1.y * scale;
            dst[4] = f2.x * scale; dst[5] = f2.y * scale;
            dst[6] = f3.x * scale; dst[7] = f3.y * scale;
        } else {
            dst[0] = f0.x; dst[1] = f0.y; dst[2] = f1.x; dst[3] = f1.y;
            dst[4] = f2.x; dst[5] = f2.y; dst[6] = f3.x; dst[7] = f3.y;
        }
    }
    for (int idx = t; idx < 169; idx += 128) bias_s[idx] = rpb[idx * NHD + h];
    if (t < NTOK) {
        int w = bw & 255;
        int hs = (w >> 3) * WS_ + t / WS_;
        int ws = (w & 7) * WS_ + t % WS_;
        int rc = hs < (GH - WS_) ? 0 : (hs < (GH - SS_) ? 1 : 2);
        int cc = ws < (GW - WS_) ? 0 : (ws < (GW - SS_) ? 1 : 2);
        reg_s[t] = rc * 3 + cc;
    }
    __syncthreads();

    for (int idx = t; idx < NTOK * NTOK; idx += 128) {
        int i = idx / NTOK, j = idx - i * NTOK;
        float s = 0.f;
        #pragma unroll
        for (int d = 0; d < HD; d++) s = fmaf(qs[i][d], ks[j][d], s);
        int yi = i / 7, xi = i - yi * 7, yj = j / 7, xj = j - yj * 7;
        s += bias_s[(yi - yj + 6) * 13 + (xi - xj + 6)];
        if (reg_s[i] != reg_s[j]) s -= 100.f;
        S[i][j] = s;
    }
    __syncthreads();

    int wid = t >> 5, lane = t & 31;
    for (int i = wid; i < NTOK; i += 4) {
        float v0 = S[i][lane];
        float v1 = (lane < NTOK - 32) ? S[i][lane + 32] : -1e30f;
        float mx = fmaxf(v0, v1);
        #pragma unroll
        for (int o = 16; o; o >>= 1) mx = fmaxf(mx, __shfl_xor_sync(0xffffffffu, mx, o));
        float e0 = __expf(v0 - mx);
        float e1 = (lane < NTOK - 32) ? __expf(v1 - mx) : 0.f;
        float sm = e0 + e1;
        #pragma unroll
        for (int o = 16; o; o >>= 1) sm += __shfl_xor_sync(0xffffffffu, sm, o);
        float inv = 1.f / sm;
        S[i][lane] = e0 * inv;
        if (lane < NTOK - 32) S[i][lane + 32] = e1 * inv;
    }
    __syncthreads();

    __half* yout = g_y_h + (size_t)bw * NTOK * CC + h * HD;
    for (int idx = t; idx < NTOK * HD; idx += 128) {
        int i = idx >> 5, d = idx & 31;
        float s = 0.f;
        #pragma unroll
        for (int j = 0; j < NTOK; j++) s = fmaf(S[i][j], vs[j][d], s);
        yout[(size_t)i * CC + d] = __float2half(s);
    }
}

// ---------------- launch ----------------
extern "C" void kernel_launch(void* const* d_in, const int* in_sizes, int n_in,
                              void* d_out, int out_size)
{
    const float* x1    = (const float*)d_in[0];
    const float* n1g   = (const float*)d_in[2];
    const float* n1b   = (const float*)d_in[3];
    const float* qkvw  = (const float*)d_in[4];
    const float* qkvb  = (const float*)d_in[5];
    const float* projw = (const float*)d_in[6];
    const float* projb = (const float*)d_in[7];
    const float* rpb   = (const float*)d_in[8];
    const float* n2g   = (const float*)d_in[9];
    const float* n2b   = (const float*)d_in[10];
    const float* fc1w  = (const float*)d_in[11];
    const float* fc1b  = (const float*)d_in[12];
    const float* fc2w  = (const float*)d_in[13];
    const float* fc2b  = (const float*)d_in[14];
    float* out = (float*)d_out;
    float* out2 = (out_size >= 2 * BLC) ? out + BLC : nullptr;

    __half *p_xw, *p_qkv, *p_y, *p_xn2, *p_h;
    __half *p_wqkv, *p_wproj, *p_wfc1, *p_wfc2;
    float *p_x1m;
    cudaGetSymbolAddress((void**)&p_xw,   g_xw_h);
    cudaGetSymbolAddress((void**)&p_qkv,  g_qkv_h);
    cudaGetSymbolAddress((void**)&p_y,    g_y_h);
    cudaGetSymbolAddress((void**)&p_x1m,  g_x1m);
    cudaGetSymbolAddress((void**)&p_xn2,  g_xn2_h);
    cudaGetSymbolAddress((void**)&p_h,    g_h_h);
    cudaGetSymbolAddress((void**)&p_wqkv, g_wqkv);
    cudaGetSymbolAddress((void**)&p_wproj,g_wproj);
    cudaGetSymbolAddress((void**)&p_wfc1, g_wfc1);
    cudaGetSymbolAddress((void**)&p_wfc2, g_wfc2);

    cudaFuncSetAttribute(k_gemm_h<0>, cudaFuncAttributeMaxDynamicSharedMemorySize, GEMM_SMEM);
    cudaFuncSetAttribute(k_gemm_h<1>, cudaFuncAttributeMaxDynamicSharedMemorySize, GEMM_SMEM);
    cudaFuncSetAttribute(k_gemm_h<2>, cudaFuncAttributeMaxDynamicSharedMemorySize, GEMM_SMEM);
    cudaFuncSetAttribute(k_gemm_h<3>, cudaFuncAttributeMaxDynamicSharedMemorySize, GEMM_SMEM);

    // 0) all weights fp32 -> fp16 (one kernel)
    k_f2h_all<<<(NQ_TOT + 255) / 256, 256>>>(qkvw, projw, fc1w, fc2w,
                                             p_wqkv, p_wproj, p_wfc1, p_wfc2);

    // 1) LN1 + shift + window partition (half out)
    k_ln1_shift_win<<<MROWS, 256>>>(x1, n1g, n1b);

    // 2) QKV
    k_gemm_h<0><<<dim3(3 * CC / BN, MROWS / BM), 256, GEMM_SMEM>>>(
        p_xw, p_wqkv, qkvb, p_qkv, 3 * CC, CC, nullptr, nullptr);

    // 3) window attention
    k_attn<<<BW * NHD, 128>>>(rpb);

    // 4) proj + window reverse + unshift + residual (+ tuple out y)
    k_gemm_h<3><<<dim3(CC / BN, MROWS / BM), 256, GEMM_SMEM>>>(
        p_y, p_wproj, projb, p_x1m, CC, CC, x1, out2);

    // 5) LN2 (half out)
    k_ln2<<<BB * LL, 256>>>(n2g, n2b);

    // 6) FC1 + GELU (half out)
    k_gemm_h<1><<<dim3(HID_ / BN, MROWS / BM), 256, GEMM_SMEM>>>(
        p_xn2, p_wfc1, fc1b, p_h, HID_, CC, nullptr, nullptr);

    // 7) FC2 + residual -> final (fp32)
    k_gemm_h<2><<<dim3(CC / BN, MROWS / BM), 256, GEMM_SMEM>>>(
        p_h, p_wfc2, fc2b, out, CC, HID_, p_x1m, nullptr);
}

// round 12
// speedup vs baseline: 4.2608x; 1.1851x over previous
#include <cuda_runtime.h>
#include <cuda_fp16.h>
#include <math.h>

// ---------------- problem constants ----------------
#define BB   4
#define TT   4
#define HH   56
#define WW_  56
#define CC   256
#define NHD  8
#define HD   32
#define WS_  7
#define SS_  3
#define NTOK 49
#define HID_ 1024
#define GH   224
#define GW   56
#define NW   256
#define BW   1024
#define MROWS (BW*NTOK)         // 50176
#define LL   (TT*HH*WW_)        // 12544
#define BLC  (BB*LL*CC)         // 12845056

// ---------------- scratch ----------------
__device__ __align__(16) __half g_xw_h [MROWS * CC];
__device__ __align__(16) __half g_qkv_h[MROWS * 3*CC];
__device__ __align__(16) __half g_y_h  [MROWS * CC];
__device__ float g_x1m [BB*LL*CC];
__device__ __align__(16) __half g_xn2_h[BB*LL*CC];
__device__ __align__(16) __half g_h_h  [BB*LL*HID_];
__device__ __align__(16) __half g_wqkv[3*CC*CC];
__device__ __align__(16) __half g_wproj[CC*CC];
__device__ __align__(16) __half g_wfc1[HID_*CC];
__device__ __align__(16) __half g_wfc2[CC*HID_];

// ---------------- fused weight convert ----------------
#define NQ_QKV (3*CC*CC/4)
#define NQ_PROJ (CC*CC/4)
#define NQ_FC1 (HID_*CC/4)
#define NQ_FC2 (CC*HID_/4)
#define NQ_TOT (NQ_QKV+NQ_PROJ+NQ_FC1+NQ_FC2)

__global__ __launch_bounds__(256) void k_f2h_all(
    const float* __restrict__ qkvw, const float* __restrict__ projw,
    const float* __restrict__ fc1w, const float* __restrict__ fc2w,
    __half* __restrict__ dqkv, __half* __restrict__ dproj,
    __half* __restrict__ dfc1, __half* __restrict__ dfc2)
{
    int i = blockIdx.x * 256 + threadIdx.x;
    if (i >= NQ_TOT) return;
    const float* src; __half* dst; int j = i;
    if (j < NQ_QKV)                 { src = qkvw; dst = dqkv; }
    else if ((j -= NQ_QKV) < NQ_PROJ) { src = projw; dst = dproj; }
    else if ((j -= NQ_PROJ) < NQ_FC1) { src = fc1w; dst = dfc1; }
    else { j -= NQ_FC1; src = fc2w; dst = dfc2; }
    float4 v = ((const float4*)src)[j];
    ((__half2*)dst)[2 * j]     = __floats2half2_rn(v.x, v.y);
    ((__half2*)dst)[2 * j + 1] = __floats2half2_rn(v.z, v.w);
}

// ---------------- LN: one warp per row, float4, warp-only reduce ----------------
// each thread: floats [lane*4 .. +3] and [128 + lane*4 .. +3] of a 256-wide row
__device__ __forceinline__ void warp_ln(const float4 v0, const float4 v1,
                                        float& mean, float& rstd) {
    float s  = v0.x + v0.y + v0.z + v0.w + v1.x + v1.y + v1.z + v1.w;
    float sq = v0.x*v0.x + v0.y*v0.y + v0.z*v0.z + v0.w*v0.w
             + v1.x*v1.x + v1.y*v1.y + v1.z*v1.z + v1.w*v1.w;
    #pragma unroll
    for (int o = 16; o; o >>= 1) {
        s  += __shfl_xor_sync(0xffffffffu, s,  o);
        sq += __shfl_xor_sync(0xffffffffu, sq, o);
    }
    mean = s * (1.0f / CC);
    float var = sq * (1.0f / CC) - mean * mean;
    rstd = rsqrtf(var + 1e-5f);
}
__device__ __forceinline__ void ln_emit_h(__half* dst, float4 v0, float4 v1,
                                          const float4 g0, const float4 g1,
                                          const float4 b0, const float4 b1,
                                          float m, float rs, int lane) {
    float4 o0, o1;
    o0.x = (v0.x - m) * rs * g0.x + b0.x; o0.y = (v0.y - m) * rs * g0.y + b0.y;
    o0.z = (v0.z - m) * rs * g0.z + b0.z; o0.w = (v0.w - m) * rs * g0.w + b0.w;
    o1.x = (v1.x - m) * rs * g1.x + b1.x; o1.y = (v1.y - m) * rs * g1.y + b1.y;
    o1.z = (v1.z - m) * rs * g1.z + b1.z; o1.w = (v1.w - m) * rs * g1.w + b1.w;
    __half2* d0 = (__half2*)(dst + lane * 4);
    d0[0] = __floats2half2_rn(o0.x, o0.y);
    d0[1] = __floats2half2_rn(o0.z, o0.w);
    __half2* d1 = (__half2*)(dst + 128 + lane * 4);
    d1[0] = __floats2half2_rn(o1.x, o1.y);
    d1[1] = __floats2half2_rn(o1.z, o1.w);
}

__global__ __launch_bounds__(256) void k_ln1_shift_win(
    const float* __restrict__ x1, const float* __restrict__ g, const float* __restrict__ b)
{
    int warp = threadIdx.x >> 5, lane = threadIdx.x & 31;
    int row = blockIdx.x * 8 + warp;
    int bw = row / NTOK, n = row - bw * NTOK;
    int bat = bw >> 8, w = bw & 255;
    int hs = (w >> 3) * WS_ + n / WS_;
    int ws = (w & 7) * WS_ + n % WS_;
    int h0 = hs + SS_; if (h0 >= GH) h0 -= GH;
    int w0 = ws + SS_; if (w0 >= GW) w0 -= GW;
    const float4* src = (const float4*)(x1 + ((size_t)bat * LL + (size_t)h0 * GW + w0) * CC);
    float4 v0 = src[lane], v1 = src[lane + 32];
    float m, rs; warp_ln(v0, v1, m, rs);
    float4 g0 = ((const float4*)g)[lane], g1 = ((const float4*)g)[lane + 32];
    float4 b0 = ((const float4*)b)[lane], b1 = ((const float4*)b)[lane + 32];
    ln_emit_h(g_xw_h + (size_t)row * CC, v0, v1, g0, g1, b0, b1, m, rs, lane);
}

__global__ __launch_bounds__(256) void k_ln2(
    const float* __restrict__ g, const float* __restrict__ b)
{
    int warp = threadIdx.x >> 5, lane = threadIdx.x & 31;
    int row = blockIdx.x * 8 + warp;
    const float4* src = (const float4*)(g_x1m + (size_t)row * CC);
    float4 v0 = src[lane], v1 = src[lane + 32];
    float m, rs; warp_ln(v0, v1, m, rs);
    float4 g0 = ((const float4*)g)[lane], g1 = ((const float4*)g)[lane + 32];
    float4 b0 = ((const float4*)b)[lane], b1 = ((const float4*)b)[lane + 32];
    ln_emit_h(g_xn2_h + (size_t)row * CC, v0, v1, g0, g1, b0, b1, m, rs, lane);
}

// ================= fp16 mma GEMM (unchanged from R11) =================
#define BM 128
#define BN 128
#define BK 64
#define SROW 72
#define MAT_H (BM * SROW)
#define STAGE_B (2 * MAT_H * 2)
#define GEMM_SMEM (2 * STAGE_B)

__device__ __forceinline__ unsigned smem_u32(const void* p) {
    unsigned a;
    asm("{ .reg .u64 t; cvta.to.shared.u64 t, %1; cvt.u32.u64 %0, t; }" : "=r"(a) : "l"(p));
    return a;
}
__device__ __forceinline__ void cp16(unsigned dst, const void* src) {
    asm volatile("cp.async.cg.shared.global [%0], [%1], 16;" :: "r"(dst), "l"(src));
}
#define CP_COMMIT() asm volatile("cp.async.commit_group;" ::: "memory")

__device__ __forceinline__ void mma16816(float* c, const unsigned* a, unsigned b0, unsigned b1) {
    asm volatile("mma.sync.aligned.m16n8k16.row.col.f32.f16.f16.f32 "
                 "{%0,%1,%2,%3}, {%4,%5,%6,%7}, {%8,%9}, {%0,%1,%2,%3};"
                 : "+f"(c[0]), "+f"(c[1]), "+f"(c[2]), "+f"(c[3])
                 : "r"(a[0]), "r"(a[1]), "r"(a[2]), "r"(a[3]), "r"(b0), "r"(b1));
}
__device__ __forceinline__ void ldsm4(unsigned* r, unsigned addr) {
    asm volatile("ldmatrix.sync.aligned.m8n8.x4.shared.b16 {%0,%1,%2,%3}, [%4];"
                 : "=r"(r[0]), "=r"(r[1]), "=r"(r[2]), "=r"(r[3]) : "r"(addr));
}

template<int EPI>
__global__ __launch_bounds__(256, 2) void k_gemm_h(
    const __half* __restrict__ A, const __half* __restrict__ Wt,
    const float* __restrict__ bias, void* __restrict__ CoutV,
    int Ntot, int K,
    const float* __restrict__ res, float* __restrict__ out2)
{
    extern __shared__ __half dsm[];
    unsigned sA = smem_u32(dsm);
    unsigned sB = sA + MAT_H * 2;

    int t = threadIdx.x, lane = t & 31, warp = t >> 5;
    int wm = (warp & 3) * 32, wn = (warp >> 2) * 64;
    int grp = lane >> 2, qid = lane & 3;
    int m0 = blockIdx.y * BM, n0 = blockIdx.x * BN;

    float acc[2][8][4];
    #pragma unroll
    for (int mt = 0; mt < 2; mt++)
        #pragma unroll
        for (int nt = 0; nt < 8; nt++)
            #pragma unroll
            for (int i = 0; i < 4; i++) acc[mt][nt][i] = 0.f;

    int lrow = t >> 3, lseg = t & 7;
    const __half* Ap = A  + (size_t)(m0 + lrow) * K + lseg * 8;
    const __half* Bp = Wt + (size_t)(n0 + lrow) * K + lseg * 8;
    unsigned dA = sA + (lrow * SROW + lseg * 8) * 2;
    unsigned dB = sB + (lrow * SROW + lseg * 8) * 2;
    const unsigned dstep = 32 * SROW * 2;

    int ar = (lane & 7) + ((lane >> 3) & 1) * 8, ac = (lane >> 4) * 8;
    int aoff = (wm + ar) * SROW + ac;
    int br = (lane & 7) + (lane >> 4) * 8, bc = ((lane >> 3) & 1) * 8;
    int boff = (wn + br) * SROW + bc;

    #pragma unroll
    for (int i = 0; i < 4; i++) {
        cp16(dA + i * dstep, Ap + (size_t)(32 * i) * K);
        cp16(dB + i * dstep, Bp + (size_t)(32 * i) * K);
    }
    CP_COMMIT();

    int nk = K / BK;
    for (int ck = 0; ck < nk; ck++) {
        unsigned stg = (ck & 1) ? STAGE_B : 0;
        if (ck + 1 < nk) {
            unsigned stg1 = ((ck + 1) & 1) ? STAGE_B : 0;
            int k1 = (ck + 1) * BK;
            #pragma unroll
            for (int i = 0; i < 4; i++) {
                cp16(dA + stg1 + i * dstep, Ap + (size_t)(32 * i) * K + k1);
                cp16(dB + stg1 + i * dstep, Bp + (size_t)(32 * i) * K + k1);
            }
            CP_COMMIT();
            asm volatile("cp.async.wait_group 1;" ::: "memory");
        } else {
            asm volatile("cp.async.wait_group 0;" ::: "memory");
        }
        __syncthreads();

        unsigned aA = sA + stg, aB = sB + stg;
        #pragma unroll
        for (int ks = 0; ks < 4; ks++) {
            unsigned a[2][4];
            ldsm4(a[0], aA + (aoff + ks * 16) * 2);
            ldsm4(a[1], aA + (aoff + 16 * SROW + ks * 16) * 2);
            #pragma unroll
            for (int np = 0; np < 4; np++) {
                unsigned bf[4];
                ldsm4(bf, aB + (boff + np * 16 * SROW + ks * 16) * 2);
                mma16816(acc[0][np * 2    ], a[0], bf[0], bf[1]);
                mma16816(acc[0][np * 2 + 1], a[0], bf[2], bf[3]);
                mma16816(acc[1][np * 2    ], a[1], bf[0], bf[1]);
                mma16816(acc[1][np * 2 + 1], a[1], bf[2], bf[3]);
            }
        }
        __syncthreads();
    }

    #pragma unroll
    for (int mt = 0; mt < 2; mt++) {
        #pragma unroll
        for (int half = 0; half < 2; half++) {
            int r = m0 + wm + mt * 16 + grp + half * 8;
            size_t dstrow = 0;
            if (EPI == 3) {
                int bw = r / NTOK, n = r - bw * NTOK;
                int bat = bw >> 8, w = bw & 255;
                int hs = (w >> 3) * WS_ + n / WS_;
                int ws = (w & 7) * WS_ + n % WS_;
                int h0 = hs + SS_; if (h0 >= GH) h0 -= GH;
                int w0 = ws + SS_; if (w0 >= GW) w0 -= GW;
                dstrow = ((size_t)bat * LL + (size_t)h0 * GW + w0) * CC;
            }
            #pragma unroll
            for (int nt = 0; nt < 8; nt++) {
                int c = n0 + wn + nt * 8 + qid * 2;
                float v0 = acc[mt][nt][half * 2 + 0] + bias[c];
                float v1 = acc[mt][nt][half * 2 + 1] + bias[c + 1];
                if (EPI == 0) {
                    *(__half2*)((__half*)CoutV + (size_t)r * Ntot + c) = __floats2half2_rn(v0, v1);
                } else if (EPI == 1) {
                    v0 = 0.5f * v0 * (1.0f + erff(v0 * 0.70710678118654752f));
                    v1 = 0.5f * v1 * (1.0f + erff(v1 * 0.70710678118654752f));
                    *(__half2*)((__half*)CoutV + (size_t)r * Ntot + c) = __floats2half2_rn(v0, v1);
                } else if (EPI == 2) {
                    float* Cout = (float*)CoutV;
                    float2 rr = *(const float2*)(res + (size_t)r * Ntot + c);
                    *(float2*)(Cout + (size_t)r * Ntot + c) = make_float2(rr.x + v0, rr.y + v1);
                } else {
                    float* Cout = (float*)CoutV;
                    size_t off = dstrow + c;
                    if (out2) *(float2*)(out2 + off) = make_float2(v0, v1);
                    float2 rr = *(const float2*)(res + off);
                    *(float2*)(Cout + off) = make_float2(rr.x + v0, rr.y + v1);
                }
            }
        }
    }
}

// ---------------- window attention: register-tiled, float4 smem ----------------
#define QP 36     // qs/ks/vs row stride (floats): 16B-aligned rows, conflict-free
#define SP 52     // S row stride
#define NPAD 52   // padded row count

__global__ __launch_bounds__(128) void k_attn(const float* __restrict__ rpb)
{
    int bw = blockIdx.x >> 3;
    int h  = blockIdx.x & 7;
    __shared__ float qs[NPAD][QP];
    __shared__ float ks[NPAD][QP];
    __shared__ float vs[NPAD][QP];
    __shared__ float S [NPAD][SP];
    __shared__ float bias_s[169];
    __shared__ int   reg_s[NPAD];
    int t = threadIdx.x;
    const float scale = 0.17677669529663687f;

    const __half* base = g_qkv_h + (size_t)bw * NTOK * (3 * CC) + h * HD;
    for (int idx = t; idx < 3 * NTOK * 4; idx += 128) {
        int mat = idx / (NTOK * 4), ch = idx - mat * NTOK * 4;
        int n = ch >> 2, seg = ch & 3;
        uint4 u = *(const uint4*)(base + (size_t)n * (3 * CC) + mat * CC + seg * 8);
        float2 f0 = __half22float2(*(__half2*)&u.x);
        float2 f1 = __half22float2(*(__half2*)&u.y);
        float2 f2 = __half22float2(*(__half2*)&u.z);
        float2 f3 = __half22float2(*(__half2*)&u.w);
        float* dst = (mat == 0 ? &qs[n][seg * 8] : mat == 1 ? &ks[n][seg * 8] : &vs[n][seg * 8]);
        if (mat == 0) {
            dst[0] = f0.x * scale; dst[1] = f0.y * scale;
            dst[2] = f1.x * scale; dst[3] = f1.y * scale;
            dst[4] = f2.x * scale; dst[5] = f2.y * scale;
            dst[6] = f3.x * scale; dst[7] = f3.y * scale;
        } else {
            dst[0] = f0.x; dst[1] = f0.y; dst[2] = f1.x; dst[3] = f1.y;
            dst[4] = f2.x; dst[5] = f2.y; dst[6] = f3.x; dst[7] = f3.y;
        }
    }
    for (int idx = t; idx < 169; idx += 128) bias_s[idx] = rpb[idx * NHD + h];
    if (t < NPAD) {
        int rv = 0;
        if (t < NTOK) {
            int w = bw & 255;
            int hs = (w >> 3) * WS_ + t / WS_;
            int ws = (w & 7) * WS_ + t % WS_;
            int rc = hs < (GH - WS_) ? 0 : (hs < (GH - SS_) ? 1 : 2);
            int cc = ws < (GW - WS_) ? 0 : (ws < (GW - SS_) ? 1 : 2);
            rv = rc * 3 + cc;
        }
        reg_s[t] = rv;
    }
    __syncthreads();

    // S = q @ k^T (+bias, +mask): 13x13 tiles of 4x4
    for (int tile = t; tile < 169; tile += 128) {
        int it = tile / 13, jt = tile - it * 13;
        int i0 = it * 4, j0 = jt * 4;
        float a[4][4];
        #pragma unroll
        for (int ii = 0; ii < 4; ii++)
            #pragma unroll
            for (int jj = 0; jj < 4; jj++) a[ii][jj] = 0.f;
        #pragma unroll
        for (int dc = 0; dc < 8; dc++) {
            float4 qv[4], kv[4];
            #pragma unroll
            for (int r = 0; r < 4; r++) qv[r] = *(const float4*)&qs[i0 + r][dc * 4];
            #pragma unroll
            for (int r = 0; r < 4; r++) kv[r] = *(const float4*)&ks[j0 + r][dc * 4];
            #pragma unroll
            for (int ii = 0; ii < 4; ii++)
                #pragma unroll
                for (int jj = 0; jj < 4; jj++) {
                    a[ii][jj] = fmaf(qv[ii].x, kv[jj].x, a[ii][jj]);
                    a[ii][jj] = fmaf(qv[ii].y, kv[jj].y, a[ii][jj]);
                    a[ii][jj] = fmaf(qv[ii].z, kv[jj].z, a[ii][jj]);
                    a[ii][jj] = fmaf(qv[ii].w, kv[jj].w, a[ii][jj]);
                }
        }
        #pragma unroll
        for (int ii = 0; ii < 4; ii++) {
            int i = i0 + ii;
            int yi = i / 7, xi = i - yi * 7, ri = reg_s[i];
            float4 o;
            float* op = &o.x;
            #pragma unroll
            for (int jj = 0; jj < 4; jj++) {
                int j = j0 + jj;
                float s = a[ii][jj];
                if (i < NTOK && j < NTOK) {
                    int yj = j / 7, xj = j - yj * 7;
                    s += bias_s[(yi - yj + 6) * 13 + (xi - xj + 6)];
                    if (ri != reg_s[j]) s -= 100.f;
                }
                op[jj] = s;
            }
            *(float4*)&S[i][j0] = o;
        }
    }
    __syncthreads();

    // softmax rows
    int wid = t >> 5, lane = t & 31;
    for (int i = wid; i < NTOK; i += 4) {
        float v0 = S[i][lane];
        float v1 = (lane < NTOK - 32) ? S[i][lane + 32] : -1e30f;
        float mx = fmaxf(v0, v1);
        #pragma unroll
        for (int o = 16; o; o >>= 1) mx = fmaxf(mx, __shfl_xor_sync(0xffffffffu, mx, o));
        float e0 = __expf(v0 - mx);
        float e1 = (lane < NTOK - 32) ? __expf(v1 - mx) : 0.f;
        float sm = e0 + e1;
        #pragma unroll
        for (int o = 16; o; o >>= 1) sm += __shfl_xor_sync(0xffffffffu, sm, o);
        float inv = 1.f / sm;
        S[i][lane] = e0 * inv;
        if (lane < NTOK - 32) S[i][lane + 32] = e1 * inv;
    }
    __syncthreads();

    // y = S @ v : 49 rows x 8 d-quads = 392 thread-tiles
    __half* yout = g_y_h + (size_t)bw * NTOK * CC + h * HD;
    for (int tile = t; tile < NTOK * 8; tile += 128) {
        int i = tile >> 3, d0 = (tile & 7) * 4;
        float4 acc4 = make_float4(0.f, 0.f, 0.f, 0.f);
        #pragma unroll 7
        for (int j = 0; j < NTOK; j++) {
            float sv = S[i][j];
            float4 vv = *(const float4*)&vs[j][d0];
            acc4.x = fmaf(sv, vv.x, acc4.x);
            acc4.y = fmaf(sv, vv.y, acc4.y);
            acc4.z = fmaf(sv, vv.z, acc4.z);
            acc4.w = fmaf(sv, vv.w, acc4.w);
        }
        __half2* d = (__half2*)(yout + (size_t)i * CC + d0);
        d[0] = __floats2half2_rn(acc4.x, acc4.y);
        d[1] = __floats2half2_rn(acc4.z, acc4.w);
    }
}

// ---------------- launch ----------------
extern "C" void kernel_launch(void* const* d_in, const int* in_sizes, int n_in,
                              void* d_out, int out_size)
{
    const float* x1    = (const float*)d_in[0];
    const float* n1g   = (const float*)d_in[2];
    const float* n1b   = (const float*)d_in[3];
    const float* qkvw  = (const float*)d_in[4];
    const float* qkvb  = (const float*)d_in[5];
    const float* projw = (const float*)d_in[6];
    const float* projb = (const float*)d_in[7];
    const float* rpb   = (const float*)d_in[8];
    const float* n2g   = (const float*)d_in[9];
    const float* n2b   = (const float*)d_in[10];
    const float* fc1w  = (const float*)d_in[11];
    const float* fc1b  = (const float*)d_in[12];
    const float* fc2w  = (const float*)d_in[13];
    const float* fc2b  = (const float*)d_in[14];
    float* out = (float*)d_out;
    float* out2 = (out_size >= 2 * BLC) ? out + BLC : nullptr;

    __half *p_xw, *p_qkv, *p_y, *p_xn2, *p_h;
    __half *p_wqkv, *p_wproj, *p_wfc1, *p_wfc2;
    float *p_x1m;
    cudaGetSymbolAddress((void**)&p_xw,   g_xw_h);
    cudaGetSymbolAddress((void**)&p_qkv,  g_qkv_h);
    cudaGetSymbolAddress((void**)&p_y,    g_y_h);
    cudaGetSymbolAddress((void**)&p_x1m,  g_x1m);
    cudaGetSymbolAddress((void**)&p_xn2,  g_xn2_h);
    cudaGetSymbolAddress((void**)&p_h,    g_h_h);
    cudaGetSymbolAddress((void**)&p_wqkv, g_wqkv);
    cudaGetSymbolAddress((void**)&p_wproj,g_wproj);
    cudaGetSymbolAddress((void**)&p_wfc1, g_wfc1);
    cudaGetSymbolAddress((void**)&p_wfc2, g_wfc2);

    cudaFuncSetAttribute(k_gemm_h<0>, cudaFuncAttributeMaxDynamicSharedMemorySize, GEMM_SMEM);
    cudaFuncSetAttribute(k_gemm_h<1>, cudaFuncAttributeMaxDynamicSharedMemorySize, GEMM_SMEM);
    cudaFuncSetAttribute(k_gemm_h<2>, cudaFuncAttributeMaxDynamicSharedMemorySize, GEMM_SMEM);
    cudaFuncSetAttribute(k_gemm_h<3>, cudaFuncAttributeMaxDynamicSharedMemorySize, GEMM_SMEM);

    // 0) weights fp32 -> fp16
    k_f2h_all<<<(NQ_TOT + 255) / 256, 256>>>(qkvw, projw, fc1w, fc2w,
                                             p_wqkv, p_wproj, p_wfc1, p_wfc2);

    // 1) LN1 + shift + window partition (warp-per-row)
    k_ln1_shift_win<<<MROWS / 8, 256>>>(x1, n1g, n1b);

    // 2) QKV
    k_gemm_h<0><<<dim3(3 * CC / BN, MROWS / BM), 256, GEMM_SMEM>>>(
        p_xw, p_wqkv, qkvb, p_qkv, 3 * CC, CC, nullptr, nullptr);

    // 3) window attention
    k_attn<<<BW * NHD, 128>>>(rpb);

    // 4) proj + window reverse + unshift + residual (+ tuple out y)
    k_gemm_h<3><<<dim3(CC / BN, MROWS / BM), 256, GEMM_SMEM>>>(
        p_y, p_wproj, projb, p_x1m, CC, CC, x1, out2);

    // 5) LN2 (warp-per-row)
    k_ln2<<<MROWS / 8, 256>>>(n2g, n2b);

    // 6) FC1 + GELU
    k_gemm_h<1><<<dim3(HID_ / BN, MROWS / BM), 256, GEMM_SMEM>>>(
        p_xn2, p_wfc1, fc1b, p_h, HID_, CC, nullptr, nullptr);

    // 7) FC2 + residual -> final
    k_gemm_h<2><<<dim3(CC / BN, MROWS / BM), 256, GEMM_SMEM>>>(
        p_h, p_wfc2, fc2b, out, CC, HID_, p_x1m, nullptr);
}

// round 13
// speedup vs baseline: 4.8654x; 1.1419x over previous
#include <cuda_runtime.h>
#include <cuda_fp16.h>
#include <math.h>

// ---------------- problem constants ----------------
#define BB   4
#define TT   4
#define HH   56
#define WW_  56
#define CC   256
#define NHD  8
#define HD   32
#define WS_  7
#define SS_  3
#define NTOK 49
#define HID_ 1024
#define GH   224
#define GW   56
#define NW   256
#define BW   1024
#define MROWS (BW*NTOK)         // 50176
#define LL   (TT*HH*WW_)        // 12544
#define BLC  (BB*LL*CC)         // 12845056

// ---------------- scratch ----------------
__device__ __align__(16) __half g_xw_h [MROWS * CC];
__device__ __align__(16) __half g_qkv_h[MROWS * 3*CC];
__device__ __align__(16) __half g_y_h  [MROWS * CC];
__device__ float g_x1m [BB*LL*CC];
__device__ __align__(16) __half g_xn2_h[BB*LL*CC];
__device__ __align__(16) __half g_h_h  [BB*LL*HID_];
__device__ __align__(16) __half g_wqkv[3*CC*CC];
__device__ __align__(16) __half g_wproj[CC*CC];
__device__ __align__(16) __half g_wfc1[HID_*CC];
__device__ __align__(16) __half g_wfc2[CC*HID_];

// ---------------- fused weight convert ----------------
#define NQ_QKV (3*CC*CC/4)
#define NQ_PROJ (CC*CC/4)
#define NQ_FC1 (HID_*CC/4)
#define NQ_FC2 (CC*HID_/4)
#define NQ_TOT (NQ_QKV+NQ_PROJ+NQ_FC1+NQ_FC2)

__global__ __launch_bounds__(256) void k_f2h_all(
    const float* __restrict__ qkvw, const float* __restrict__ projw,
    const float* __restrict__ fc1w, const float* __restrict__ fc2w,
    __half* __restrict__ dqkv, __half* __restrict__ dproj,
    __half* __restrict__ dfc1, __half* __restrict__ dfc2)
{
    int i = blockIdx.x * 256 + threadIdx.x;
    if (i >= NQ_TOT) return;
    const float* src; __half* dst; int j = i;
    if (j < NQ_QKV)                 { src = qkvw; dst = dqkv; }
    else if ((j -= NQ_QKV) < NQ_PROJ) { src = projw; dst = dproj; }
    else if ((j -= NQ_PROJ) < NQ_FC1) { src = fc1w; dst = dfc1; }
    else { j -= NQ_FC1; src = fc2w; dst = dfc2; }
    float4 v = ((const float4*)src)[j];
    ((__half2*)dst)[2 * j]     = __floats2half2_rn(v.x, v.y);
    ((__half2*)dst)[2 * j + 1] = __floats2half2_rn(v.z, v.w);
}

// ---------------- LN: one warp per row ----------------
__device__ __forceinline__ void warp_ln(const float4 v0, const float4 v1,
                                        float& mean, float& rstd) {
    float s  = v0.x + v0.y + v0.z + v0.w + v1.x + v1.y + v1.z + v1.w;
    float sq = v0.x*v0.x + v0.y*v0.y + v0.z*v0.z + v0.w*v0.w
             + v1.x*v1.x + v1.y*v1.y + v1.z*v1.z + v1.w*v1.w;
    #pragma unroll
    for (int o = 16; o; o >>= 1) {
        s  += __shfl_xor_sync(0xffffffffu, s,  o);
        sq += __shfl_xor_sync(0xffffffffu, sq, o);
    }
    mean = s * (1.0f / CC);
    float var = sq * (1.0f / CC) - mean * mean;
    rstd = rsqrtf(var + 1e-5f);
}
__device__ __forceinline__ void ln_emit_h(__half* dst, float4 v0, float4 v1,
                                          const float4 g0, const float4 g1,
                                          const float4 b0, const float4 b1,
                                          float m, float rs, int lane) {
    float4 o0, o1;
    o0.x = (v0.x - m) * rs * g0.x + b0.x; o0.y = (v0.y - m) * rs * g0.y + b0.y;
    o0.z = (v0.z - m) * rs * g0.z + b0.z; o0.w = (v0.w - m) * rs * g0.w + b0.w;
    o1.x = (v1.x - m) * rs * g1.x + b1.x; o1.y = (v1.y - m) * rs * g1.y + b1.y;
    o1.z = (v1.z - m) * rs * g1.z + b1.z; o1.w = (v1.w - m) * rs * g1.w + b1.w;
    __half2* d0 = (__half2*)(dst + lane * 4);
    d0[0] = __floats2half2_rn(o0.x, o0.y);
    d0[1] = __floats2half2_rn(o0.z, o0.w);
    __half2* d1 = (__half2*)(dst + 128 + lane * 4);
    d1[0] = __floats2half2_rn(o1.x, o1.y);
    d1[1] = __floats2half2_rn(o1.z, o1.w);
}

__global__ __launch_bounds__(256) void k_ln1_shift_win(
    const float* __restrict__ x1, const float* __restrict__ g, const float* __restrict__ b)
{
    int warp = threadIdx.x >> 5, lane = threadIdx.x & 31;
    int row = blockIdx.x * 8 + warp;
    int bw = row / NTOK, n = row - bw * NTOK;
    int bat = bw >> 8, w = bw & 255;
    int hs = (w >> 3) * WS_ + n / WS_;
    int ws = (w & 7) * WS_ + n % WS_;
    int h0 = hs + SS_; if (h0 >= GH) h0 -= GH;
    int w0 = ws + SS_; if (w0 >= GW) w0 -= GW;
    const float4* src = (const float4*)(x1 + ((size_t)bat * LL + (size_t)h0 * GW + w0) * CC);
    float4 v0 = src[lane], v1 = src[lane + 32];
    float m, rs; warp_ln(v0, v1, m, rs);
    float4 g0 = ((const float4*)g)[lane], g1 = ((const float4*)g)[lane + 32];
    float4 b0 = ((const float4*)b)[lane], b1 = ((const float4*)b)[lane + 32];
    ln_emit_h(g_xw_h + (size_t)row * CC, v0, v1, g0, g1, b0, b1, m, rs, lane);
}

__global__ __launch_bounds__(256) void k_ln2(
    const float* __restrict__ g, const float* __restrict__ b)
{
    int warp = threadIdx.x >> 5, lane = threadIdx.x & 31;
    int row = blockIdx.x * 8 + warp;
    const float4* src = (const float4*)(g_x1m + (size_t)row * CC);
    float4 v0 = src[lane], v1 = src[lane + 32];
    float m, rs; warp_ln(v0, v1, m, rs);
    float4 g0 = ((const float4*)g)[lane], g1 = ((const float4*)g)[lane + 32];
    float4 b0 = ((const float4*)b)[lane], b1 = ((const float4*)b)[lane + 32];
    ln_emit_h(g_xn2_h + (size_t)row * CC, v0, v1, g0, g1, b0, b1, m, rs, lane);
}

// ================= fp16 mma GEMM (unchanged) =================
#define BM 128
#define BN 128
#define BK 64
#define SROW 72
#define MAT_H (BM * SROW)
#define STAGE_B (2 * MAT_H * 2)
#define GEMM_SMEM (2 * STAGE_B)

__device__ __forceinline__ unsigned smem_u32(const void* p) {
    unsigned a;
    asm("{ .reg .u64 t; cvta.to.shared.u64 t, %1; cvt.u32.u64 %0, t; }" : "=r"(a) : "l"(p));
    return a;
}
__device__ __forceinline__ void cp16(unsigned dst, const void* src) {
    asm volatile("cp.async.cg.shared.global [%0], [%1], 16;" :: "r"(dst), "l"(src));
}
#define CP_COMMIT() asm volatile("cp.async.commit_group;" ::: "memory")

__device__ __forceinline__ void mma16816(float* c, const unsigned* a, unsigned b0, unsigned b1) {
    asm volatile("mma.sync.aligned.m16n8k16.row.col.f32.f16.f16.f32 "
                 "{%0,%1,%2,%3}, {%4,%5,%6,%7}, {%8,%9}, {%0,%1,%2,%3};"
                 : "+f"(c[0]), "+f"(c[1]), "+f"(c[2]), "+f"(c[3])
                 : "r"(a[0]), "r"(a[1]), "r"(a[2]), "r"(a[3]), "r"(b0), "r"(b1));
}
__device__ __forceinline__ void ldsm4(unsigned* r, unsigned addr) {
    asm volatile("ldmatrix.sync.aligned.m8n8.x4.shared.b16 {%0,%1,%2,%3}, [%4];"
                 : "=r"(r[0]), "=r"(r[1]), "=r"(r[2]), "=r"(r[3]) : "r"(addr));
}

template<int EPI>
__global__ __launch_bounds__(256, 2) void k_gemm_h(
    const __half* __restrict__ A, const __half* __restrict__ Wt,
    const float* __restrict__ bias, void* __restrict__ CoutV,
    int Ntot, int K,
    const float* __restrict__ res, float* __restrict__ out2)
{
    extern __shared__ __half dsm[];
    unsigned sA = smem_u32(dsm);
    unsigned sB = sA + MAT_H * 2;

    int t = threadIdx.x, lane = t & 31, warp = t >> 5;
    int wm = (warp & 3) * 32, wn = (warp >> 2) * 64;
    int grp = lane >> 2, qid = lane & 3;
    int m0 = blockIdx.y * BM, n0 = blockIdx.x * BN;

    float acc[2][8][4];
    #pragma unroll
    for (int mt = 0; mt < 2; mt++)
        #pragma unroll
        for (int nt = 0; nt < 8; nt++)
            #pragma unroll
            for (int i = 0; i < 4; i++) acc[mt][nt][i] = 0.f;

    int lrow = t >> 3, lseg = t & 7;
    const __half* Ap = A  + (size_t)(m0 + lrow) * K + lseg * 8;
    const __half* Bp = Wt + (size_t)(n0 + lrow) * K + lseg * 8;
    unsigned dA = sA + (lrow * SROW + lseg * 8) * 2;
    unsigned dB = sB + (lrow * SROW + lseg * 8) * 2;
    const unsigned dstep = 32 * SROW * 2;

    int ar = (lane & 7) + ((lane >> 3) & 1) * 8, ac = (lane >> 4) * 8;
    int aoff = (wm + ar) * SROW + ac;
    int br = (lane & 7) + (lane >> 4) * 8, bc = ((lane >> 3) & 1) * 8;
    int boff = (wn + br) * SROW + bc;

    #pragma unroll
    for (int i = 0; i < 4; i++) {
        cp16(dA + i * dstep, Ap + (size_t)(32 * i) * K);
        cp16(dB + i * dstep, Bp + (size_t)(32 * i) * K);
    }
    CP_COMMIT();

    int nk = K / BK;
    for (int ck = 0; ck < nk; ck++) {
        unsigned stg = (ck & 1) ? STAGE_B : 0;
        if (ck + 1 < nk) {
            unsigned stg1 = ((ck + 1) & 1) ? STAGE_B : 0;
            int k1 = (ck + 1) * BK;
            #pragma unroll
            for (int i = 0; i < 4; i++) {
                cp16(dA + stg1 + i * dstep, Ap + (size_t)(32 * i) * K + k1);
                cp16(dB + stg1 + i * dstep, Bp + (size_t)(32 * i) * K + k1);
            }
            CP_COMMIT();
            asm volatile("cp.async.wait_group 1;" ::: "memory");
        } else {
            asm volatile("cp.async.wait_group 0;" ::: "memory");
        }
        __syncthreads();

        unsigned aA = sA + stg, aB = sB + stg;
        #pragma unroll
        for (int ks = 0; ks < 4; ks++) {
            unsigned a[2][4];
            ldsm4(a[0], aA + (aoff + ks * 16) * 2);
            ldsm4(a[1], aA + (aoff + 16 * SROW + ks * 16) * 2);
            #pragma unroll
            for (int np = 0; np < 4; np++) {
                unsigned bf[4];
                ldsm4(bf, aB + (boff + np * 16 * SROW + ks * 16) * 2);
                mma16816(acc[0][np * 2    ], a[0], bf[0], bf[1]);
                mma16816(acc[0][np * 2 + 1], a[0], bf[2], bf[3]);
                mma16816(acc[1][np * 2    ], a[1], bf[0], bf[1]);
                mma16816(acc[1][np * 2 + 1], a[1], bf[2], bf[3]);
            }
        }
        __syncthreads();
    }

    #pragma unroll
    for (int mt = 0; mt < 2; mt++) {
        #pragma unroll
        for (int half = 0; half < 2; half++) {
            int r = m0 + wm + mt * 16 + grp + half * 8;
            size_t dstrow = 0;
            if (EPI == 3) {
                int bw = r / NTOK, n = r - bw * NTOK;
                int bat = bw >> 8, w = bw & 255;
                int hs = (w >> 3) * WS_ + n / WS_;
                int ws = (w & 7) * WS_ + n % WS_;
                int h0 = hs + SS_; if (h0 >= GH) h0 -= GH;
                int w0 = ws + SS_; if (w0 >= GW) w0 -= GW;
                dstrow = ((size_t)bat * LL + (size_t)h0 * GW + w0) * CC;
            }
            #pragma unroll
            for (int nt = 0; nt < 8; nt++) {
                int c = n0 + wn + nt * 8 + qid * 2;
                float v0 = acc[mt][nt][half * 2 + 0] + bias[c];
                float v1 = acc[mt][nt][half * 2 + 1] + bias[c + 1];
                if (EPI == 0) {
                    *(__half2*)((__half*)CoutV + (size_t)r * Ntot + c) = __floats2half2_rn(v0, v1);
                } else if (EPI == 1) {
                    v0 = 0.5f * v0 * (1.0f + erff(v0 * 0.70710678118654752f));
                    v1 = 0.5f * v1 * (1.0f + erff(v1 * 0.70710678118654752f));
                    *(__half2*)((__half*)CoutV + (size_t)r * Ntot + c) = __floats2half2_rn(v0, v1);
                } else if (EPI == 2) {
                    float* Cout = (float*)CoutV;
                    float2 rr = *(const float2*)(res + (size_t)r * Ntot + c);
                    *(float2*)(Cout + (size_t)r * Ntot + c) = make_float2(rr.x + v0, rr.y + v1);
                } else {
                    float* Cout = (float*)CoutV;
                    size_t off = dstrow + c;
                    if (out2) *(float2*)(out2 + off) = make_float2(v0, v1);
                    float2 rr = *(const float2*)(res + off);
                    *(float2*)(Cout + off) = make_float2(rr.x + v0, rr.y + v1);
                }
            }
        }
    }
}

// ---------------- window attention: fp16 smem operands, fp32 accumulation ----------------
#define QPH 40    // halves per q/k/v smem row (80B, 16B-aligned)
#define SP 52     // S row stride (floats)
#define NPAD 52

__global__ __launch_bounds__(128) void k_attn(const float* __restrict__ rpb)
{
    int bw = blockIdx.x >> 3;
    int h  = blockIdx.x & 7;
    __shared__ __half qs[NPAD][QPH];
    __shared__ __half ks[NPAD][QPH];
    __shared__ __half vs[NPAD][QPH];
    __shared__ float S [NPAD][SP];
    __shared__ float bias_s[169];
    __shared__ int   reg_s[NPAD];
    int t = threadIdx.x;
    const float scale = 0.17677669529663687f;

    // raw fp16 copy: 3 matrices x 49 rows x 4 chunks(16B)
    const __half* base = g_qkv_h + (size_t)bw * NTOK * (3 * CC) + h * HD;
    for (int idx = t; idx < 3 * NTOK * 4; idx += 128) {
        int mat = idx / (NTOK * 4), ch = idx - mat * NTOK * 4;
        int n = ch >> 2, seg = ch & 3;
        uint4 u = *(const uint4*)(base + (size_t)n * (3 * CC) + mat * CC + seg * 8);
        __half* dst = (mat == 0 ? &qs[n][0] : mat == 1 ? &ks[n][0] : &vs[n][0]);
        *(uint4*)(dst + seg * 8) = u;
    }
    for (int idx = t; idx < 169; idx += 128) bias_s[idx] = rpb[idx * NHD + h];
    if (t < NPAD) {
        int rv = 0;
        if (t < NTOK) {
            int w = bw & 255;
            int hs = (w >> 3) * WS_ + t / WS_;
            int ws = (w & 7) * WS_ + t % WS_;
            int rc = hs < (GH - WS_) ? 0 : (hs < (GH - SS_) ? 1 : 2);
            int cc = ws < (GW - WS_) ? 0 : (ws < (GW - SS_) ? 1 : 2);
            rv = rc * 3 + cc;
        }
        reg_s[t] = rv;
    }
    __syncthreads();

    // S = (q @ k^T)*scale + bias + mask : 13x13 tiles of 4x4, fp32 accumulate
    for (int tile = t; tile < 169; tile += 128) {
        int it = tile / 13, jt = tile - it * 13;
        int i0 = it * 4, j0 = jt * 4;
        float a[4][4];
        #pragma unroll
        for (int ii = 0; ii < 4; ii++)
            #pragma unroll
            for (int jj = 0; jj < 4; jj++) a[ii][jj] = 0.f;
        #pragma unroll
        for (int dc = 0; dc < 4; dc++) {       // 8 halves per chunk
            float qf[4][8], kf[4][8];
            #pragma unroll
            for (int r = 0; r < 4; r++) {
                uint4 u = *(const uint4*)(&qs[i0 + r][dc * 8]);
                float2 f0 = __half22float2(*(__half2*)&u.x);
                float2 f1 = __half22float2(*(__half2*)&u.y);
                float2 f2 = __half22float2(*(__half2*)&u.z);
                float2 f3 = __half22float2(*(__half2*)&u.w);
                qf[r][0]=f0.x; qf[r][1]=f0.y; qf[r][2]=f1.x; qf[r][3]=f1.y;
                qf[r][4]=f2.x; qf[r][5]=f2.y; qf[r][6]=f3.x; qf[r][7]=f3.y;
            }
            #pragma unroll
            for (int r = 0; r < 4; r++) {
                uint4 u = *(const uint4*)(&ks[j0 + r][dc * 8]);
                float2 f0 = __half22float2(*(__half2*)&u.x);
                float2 f1 = __half22float2(*(__half2*)&u.y);
                float2 f2 = __half22float2(*(__half2*)&u.z);
                float2 f3 = __half22float2(*(__half2*)&u.w);
                kf[r][0]=f0.x; kf[r][1]=f0.y; kf[r][2]=f1.x; kf[r][3]=f1.y;
                kf[r][4]=f2.x; kf[r][5]=f2.y; kf[r][6]=f3.x; kf[r][7]=f3.y;
            }
            #pragma unroll
            for (int ii = 0; ii < 4; ii++)
                #pragma unroll
                for (int jj = 0; jj < 4; jj++)
                    #pragma unroll
                    for (int d = 0; d < 8; d++)
                        a[ii][jj] = fmaf(qf[ii][d], kf[jj][d], a[ii][jj]);
        }
        #pragma unroll
        for (int ii = 0; ii < 4; ii++) {
            int i = i0 + ii;
            int yi = i / 7, xi = i - yi * 7, ri = reg_s[i];
            float4 o;
            float* op = &o.x;
            #pragma unroll
            for (int jj = 0; jj < 4; jj++) {
                int j = j0 + jj;
                float s = a[ii][jj] * scale;
                if (i < NTOK && j < NTOK) {
                    int yj = j / 7, xj = j - yj * 7;
                    s += bias_s[(yi - yj + 6) * 13 + (xi - xj + 6)];
                    if (ri != reg_s[j]) s -= 100.f;
                }
                op[jj] = s;
            }
            *(float4*)&S[i][j0] = o;
        }
    }
    __syncthreads();

    // softmax rows (fp32)
    int wid = t >> 5, lane = t & 31;
    for (int i = wid; i < NTOK; i += 4) {
        float v0 = S[i][lane];
        float v1 = (lane < NTOK - 32) ? S[i][lane + 32] : -1e30f;
        float mx = fmaxf(v0, v1);
        #pragma unroll
        for (int o = 16; o; o >>= 1) mx = fmaxf(mx, __shfl_xor_sync(0xffffffffu, mx, o));
        float e0 = __expf(v0 - mx);
        float e1 = (lane < NTOK - 32) ? __expf(v1 - mx) : 0.f;
        float sm = e0 + e1;
        #pragma unroll
        for (int o = 16; o; o >>= 1) sm += __shfl_xor_sync(0xffffffffu, sm, o);
        float inv = 1.f / sm;
        S[i][lane] = e0 * inv;
        if (lane < NTOK - 32) S[i][lane + 32] = e1 * inv;
    }
    __syncthreads();

    // y = S @ v : 49 rows x 4 d-chunks(8) = 196 thread-tiles, fp32 accumulate
    __half* yout = g_y_h + (size_t)bw * NTOK * CC + h * HD;
    for (int tile = t; tile < NTOK * 4; tile += 128) {
        int i = tile >> 2, d0 = (tile & 3) * 8;
        float acc8[8];
        #pragma unroll
        for (int d = 0; d < 8; d++) acc8[d] = 0.f;
        #pragma unroll 7
        for (int j = 0; j < NTOK; j++) {
            float sv = S[i][j];
            uint4 u = *(const uint4*)(&vs[j][d0]);
            float2 f0 = __half22float2(*(__half2*)&u.x);
            float2 f1 = __half22float2(*(__half2*)&u.y);
            float2 f2 = __half22float2(*(__half2*)&u.z);
            float2 f3 = __half22float2(*(__half2*)&u.w);
            acc8[0] = fmaf(sv, f0.x, acc8[0]); acc8[1] = fmaf(sv, f0.y, acc8[1]);
            acc8[2] = fmaf(sv, f1.x, acc8[2]); acc8[3] = fmaf(sv, f1.y, acc8[3]);
            acc8[4] = fmaf(sv, f2.x, acc8[4]); acc8[5] = fmaf(sv, f2.y, acc8[5]);
            acc8[6] = fmaf(sv, f3.x, acc8[6]); acc8[7] = fmaf(sv, f3.y, acc8[7]);
        }
        __half2* d = (__half2*)(yout + (size_t)i * CC + d0);
        d[0] = __floats2half2_rn(acc8[0], acc8[1]);
        d[1] = __floats2half2_rn(acc8[2], acc8[3]);
        d[2] = __floats2half2_rn(acc8[4], acc8[5]);
        d[3] = __floats2half2_rn(acc8[6], acc8[7]);
    }
}

// ---------------- launch ----------------
extern "C" void kernel_launch(void* const* d_in, const int* in_sizes, int n_in,
                              void* d_out, int out_size)
{
    const float* x1    = (const float*)d_in[0];
    const float* n1g   = (const float*)d_in[2];
    const float* n1b   = (const float*)d_in[3];
    const float* qkvw  = (const float*)d_in[4];
    const float* qkvb  = (const float*)d_in[5];
    const float* projw = (const float*)d_in[6];
    const float* projb = (const float*)d_in[7];
    const float* rpb   = (const float*)d_in[8];
    const float* n2g   = (const float*)d_in[9];
    const float* n2b   = (const float*)d_in[10];
    const float* fc1w  = (const float*)d_in[11];
    const float* fc1b  = (const float*)d_in[12];
    const float* fc2w  = (const float*)d_in[13];
    const float* fc2b  = (const float*)d_in[14];
    float* out = (float*)d_out;
    float* out2 = (out_size >= 2 * BLC) ? out + BLC : nullptr;

    __half *p_xw, *p_qkv, *p_y, *p_xn2, *p_h;
    __half *p_wqkv, *p_wproj, *p_wfc1, *p_wfc2;
    float *p_x1m;
    cudaGetSymbolAddress((void**)&p_xw,   g_xw_h);
    cudaGetSymbolAddress((void**)&p_qkv,  g_qkv_h);
    cudaGetSymbolAddress((void**)&p_y,    g_y_h);
    cudaGetSymbolAddress((void**)&p_x1m,  g_x1m);
    cudaGetSymbolAddress((void**)&p_xn2,  g_xn2_h);
    cudaGetSymbolAddress((void**)&p_h,    g_h_h);
    cudaGetSymbolAddress((void**)&p_wqkv, g_wqkv);
    cudaGetSymbolAddress((void**)&p_wproj,g_wproj);
    cudaGetSymbolAddress((void**)&p_wfc1, g_wfc1);
    cudaGetSymbolAddress((void**)&p_wfc2, g_wfc2);

    cudaFuncSetAttribute(k_gemm_h<0>, cudaFuncAttributeMaxDynamicSharedMemorySize, GEMM_SMEM);
    cudaFuncSetAttribute(k_gemm_h<1>, cudaFuncAttributeMaxDynamicSharedMemorySize, GEMM_SMEM);
    cudaFuncSetAttribute(k_gemm_h<2>, cudaFuncAttributeMaxDynamicSharedMemorySize, GEMM_SMEM);
    cudaFuncSetAttribute(k_gemm_h<3>, cudaFuncAttributeMaxDynamicSharedMemorySize, GEMM_SMEM);

    // 0) weights fp32 -> fp16
    k_f2h_all<<<(NQ_TOT + 255) / 256, 256>>>(qkvw, projw, fc1w, fc2w,
                                             p_wqkv, p_wproj, p_wfc1, p_wfc2);

    // 1) LN1 + shift + window partition
    k_ln1_shift_win<<<MROWS / 8, 256>>>(x1, n1g, n1b);

    // 2) QKV
    k_gemm_h<0><<<dim3(3 * CC / BN, MROWS / BM), 256, GEMM_SMEM>>>(
        p_xw, p_wqkv, qkvb, p_qkv, 3 * CC, CC, nullptr, nullptr);

    // 3) window attention
    k_attn<<<BW * NHD, 128>>>(rpb);

    // 4) proj + window reverse + unshift + residual (+ tuple out y)
    k_gemm_h<3><<<dim3(CC / BN, MROWS / BM), 256, GEMM_SMEM>>>(
        p_y, p_wproj, projb, p_x1m, CC, CC, x1, out2);

    // 5) LN2
    k_ln2<<<MROWS / 8, 256>>>(n2g, n2b);

    // 6) FC1 + GELU
    k_gemm_h<1><<<dim3(HID_ / BN, MROWS / BM), 256, GEMM_SMEM>>>(
        p_xn2, p_wfc1, fc1b, p_h, HID_, CC, nullptr, nullptr);

    // 7) FC2 + residual -> final
    k_gemm_h<2><<<dim3(CC / BN, MROWS / BM), 256, GEMM_SMEM>>>(
        p_h, p_wfc2, fc2b, out, CC, HID_, p_x1m, nullptr);
}